// round 3
// baseline (speedup 1.0000x reference)
#include <cuda_runtime.h>
#include <math.h>

#define NN   20000
#define EE   320000
#define DIN  128
#define HH   256
#define LL   2
#define GG   32
#define NREL 6

// ---------------- device scratch (static: no allocation allowed) ----------------
__device__ float g_x[2][NN * HH];          // current node features per type
__device__ float g_accb[2][NN * HH];       // layer accumulator per type
__device__ float g_tmp[NREL][NN * HH];     // x[st] @ W_l[i,r] per relation
__device__ float g_wrsum[2][HH * HH];      // summed W_r per dst-type group
__device__ float g_blsum[2][HH];           // summed b_l per dst-type group
__device__ int   g_deg[NREL][NN];
__device__ int   g_rowptr[NREL][NN + 1];
__device__ int   g_cursor[NREL][NN];
__device__ int   g_col[NREL][EE];
__device__ float g_stats[2][2 * HH];       // per type: [sum(256), sumsq(256)]
__device__ float g_pool[2][GG * HH];
__device__ int   g_pcnt[2][GG];
__device__ int   g_is64;                   // 1 if index arrays are int64, 0 if int32

// ---------------- small helpers ----------------
__device__ __forceinline__ float4 f4add(float4 a, float4 b) {
    return make_float4(a.x + b.x, a.y + b.y, a.z + b.z, a.w + b.w);
}
__device__ __forceinline__ float4 f4fma(float4 a, float s, float4 c) {
    return make_float4(fmaf(a.x, s, c.x), fmaf(a.y, s, c.y),
                       fmaf(a.z, s, c.z), fmaf(a.w, s, c.w));
}
__device__ __forceinline__ int idx_at(const void* p, long long i, int is64) {
    return is64 ? (int)((const long long*)p)[i] : ((const int*)p)[i];
}

// ---------------- index dtype detection ----------------
// View edge buffer as 32-bit words. If int64 (little-endian, values < 2^31),
// every odd word is 0. If int32, odd words are uniform indices in [0,20000).
__global__ void k_detect(const unsigned int* __restrict__ e) {
    __shared__ int any;
    if (threadIdx.x == 0) any = 0;
    __syncthreads();
    unsigned int v = 0;
    for (int i = threadIdx.x; i < 2048; i += blockDim.x)
        v |= e[(long long)i * 1874 + 1];   // always-odd indices, < NREL*2*EE words
    if (v) any = 1;
    __syncthreads();
    if (threadIdx.x == 0) g_is64 = any ? 0 : 1;
}

// ---------------- CSR construction ----------------
__global__ void k_hist(const void* __restrict__ edge) {
    int is64 = g_is64;
    int gid = blockIdx.x * blockDim.x + threadIdx.x;
    if (gid >= NREL * EE) return;
    int r = gid / EE, e = gid - r * EE;
    int dst = idx_at(edge, ((long long)r * 2 + 1) * EE + e, is64);
    atomicAdd(&g_deg[r][dst], 1);
}

__global__ void k_scan() {
    int r = blockIdx.x;
    __shared__ int sh[1024];
    __shared__ int carry;
    if (threadIdx.x == 0) carry = 0;
    __syncthreads();
    for (int base = 0; base < NN; base += 1024) {
        int i = base + threadIdx.x;
        int v = (i < NN) ? g_deg[r][i] : 0;
        sh[threadIdx.x] = v;
        __syncthreads();
        for (int off = 1; off < 1024; off <<= 1) {
            int t = (threadIdx.x >= off) ? sh[threadIdx.x - off] : 0;
            __syncthreads();
            sh[threadIdx.x] += t;
            __syncthreads();
        }
        int incl = sh[threadIdx.x];
        if (i < NN) {
            int ex = carry + incl - v;
            g_rowptr[r][i] = ex;
            g_cursor[r][i] = ex;
        }
        __syncthreads();
        if (threadIdx.x == 1023) carry += incl;
        __syncthreads();
    }
    if (threadIdx.x == 0) g_rowptr[r][NN] = carry;
}

__global__ void k_fill(const void* __restrict__ edge) {
    int is64 = g_is64;
    int gid = blockIdx.x * blockDim.x + threadIdx.x;
    if (gid >= NREL * EE) return;
    int r = gid / EE, e = gid - r * EE;
    int src = idx_at(edge, ((long long)r * 2 + 0) * EE + e, is64);
    int dst = idx_at(edge, ((long long)r * 2 + 1) * EE + e, is64);
    int slot = atomicAdd(&g_cursor[r][dst], 1);
    g_col[r][slot] = src;
}

// ---------------- SGEMM: C[M,256] = A[M,K] @ B[K,256] (+ bias), z-batched B/C ----------------
// BM=128, BN=64, BK=16, 256 threads, 8x4 per thread.
__global__ void __launch_bounds__(256) sgemm_bias(
    const float* __restrict__ A, const float* __restrict__ Bb,
    float* __restrict__ Cb, const float* __restrict__ bias,
    int M, int K, long long sB, long long sC)
{
    const float* B = Bb + (long long)blockIdx.z * sB;
    float* C = Cb + (long long)blockIdx.z * sC;
    __shared__ float As[16 * 128];
    __shared__ float Bs[16 * 64];
    int tid = threadIdx.x;
    int tx = tid & 15, ty = tid >> 4;
    int bm = blockIdx.x * 128, bn = blockIdx.y * 64;

    float acc[8][4];
#pragma unroll
    for (int i = 0; i < 8; i++)
#pragma unroll
        for (int j = 0; j < 4; j++) acc[i][j] = 0.0f;

    for (int k0 = 0; k0 < K; k0 += 16) {
        // A tile: 128x16 -> transposed into As[k][m]
#pragma unroll
        for (int i = 0; i < 2; i++) {
            int f = tid * 2 + i;
            int row = f >> 2, c4 = (f & 3) * 4;
            float4 v = make_float4(0.f, 0.f, 0.f, 0.f);
            if (bm + row < M)
                v = *(const float4*)&A[(long long)(bm + row) * K + k0 + c4];
            As[(c4 + 0) * 128 + row] = v.x;
            As[(c4 + 1) * 128 + row] = v.y;
            As[(c4 + 2) * 128 + row] = v.z;
            As[(c4 + 3) * 128 + row] = v.w;
        }
        // B tile: 16x64 direct
        {
            int row = tid >> 4, c4 = (tid & 15) * 4;
            float4 v = *(const float4*)&B[(long long)(k0 + row) * 256 + bn + c4];
            *(float4*)&Bs[row * 64 + c4] = v;
        }
        __syncthreads();
#pragma unroll
        for (int kk = 0; kk < 16; kk++) {
            float4 a0 = *(const float4*)&As[kk * 128 + tx * 4];
            float4 a1 = *(const float4*)&As[kk * 128 + tx * 4 + 64];
            float4 b  = *(const float4*)&Bs[kk * 64 + ty * 4];
            float av[8] = {a0.x, a0.y, a0.z, a0.w, a1.x, a1.y, a1.z, a1.w};
            float bv[4] = {b.x, b.y, b.z, b.w};
#pragma unroll
            for (int i = 0; i < 8; i++)
#pragma unroll
                for (int j = 0; j < 4; j++)
                    acc[i][j] = fmaf(av[i], bv[j], acc[i][j]);
        }
        __syncthreads();
    }

    float4 b4 = make_float4(0.f, 0.f, 0.f, 0.f);
    if (bias) b4 = *(const float4*)&bias[bn + ty * 4];
#pragma unroll
    for (int i = 0; i < 8; i++) {
        int row = bm + (i < 4 ? tx * 4 + i : 64 + tx * 4 + (i - 4));
        if (row < M) {
            float4 o = make_float4(acc[i][0] + b4.x, acc[i][1] + b4.y,
                                   acc[i][2] + b4.z, acc[i][3] + b4.w);
            *(float4*)&C[(long long)row * 256 + bn + ty * 4] = o;
        }
    }
}

// ---------------- weight/bias folding for the self path ----------------
__global__ void k_wsum(const float* __restrict__ W_r, const float* __restrict__ b_l, int layer) {
    int gid = blockIdx.x * blockDim.x + threadIdx.x;
    const int grp[2][3] = {{0, 1, 3}, {2, 4, 5}};
    if (gid < 2 * HH * HH) {
        int t = gid / (HH * HH), k = gid - t * (HH * HH);
        const float* W = W_r + (long long)layer * NREL * HH * HH;
        g_wrsum[t][k] = W[grp[t][0] * HH * HH + k] + W[grp[t][1] * HH * HH + k] +
                        W[grp[t][2] * HH * HH + k];
    }
    if (gid < 2 * HH) {
        int t = gid / HH, c = gid - t * HH;
        const float* b = b_l + (long long)layer * NREL * HH;
        g_blsum[t][c] = b[grp[t][0] * HH + c] + b[grp[t][1] * HH + c] + b[grp[t][2] * HH + c];
    }
}

// ---------------- gather-mean aggregation: acc[dst] += sum_r mean_{src in N_r(dst)} tmp[r][src] ----------------
__global__ void k_agg(int r0, int r1, int r2, float* __restrict__ acc) {
    int w = (blockIdx.x * blockDim.x + threadIdx.x) >> 5;
    int lane = threadIdx.x & 31;
    if (w >= NN) return;
    float4 t0 = make_float4(0.f, 0.f, 0.f, 0.f), t1 = t0;
    int rel[3] = {r0, r1, r2};
#pragma unroll
    for (int q = 0; q < 3; q++) {
        int r = rel[q];
        int b = g_rowptr[r][w], e = g_rowptr[r][w + 1];
        float4 s0 = make_float4(0.f, 0.f, 0.f, 0.f), s1 = s0;
        const float4* base = (const float4*)g_tmp[r];
        int j = b;
        for (; j + 1 < e; j += 2) {
            int sa = g_col[r][j], sb = g_col[r][j + 1];
            const float4* ra = base + (long long)sa * 64;
            const float4* rb = base + (long long)sb * 64;
            float4 va0 = ra[lane], va1 = ra[lane + 32];
            float4 vb0 = rb[lane], vb1 = rb[lane + 32];
            s0 = f4add(s0, f4add(va0, vb0));
            s1 = f4add(s1, f4add(va1, vb1));
        }
        if (j < e) {
            int sa = g_col[r][j];
            const float4* ra = base + (long long)sa * 64;
            s0 = f4add(s0, ra[lane]);
            s1 = f4add(s1, ra[lane + 32]);
        }
        float inv = (e > b) ? 1.0f / (float)(e - b) : 0.0f;
        t0 = f4fma(s0, inv, t0);
        t1 = f4fma(s1, inv, t1);
    }
    float4* arow = (float4*)(acc + (long long)w * HH);
    arow[lane] = f4add(arow[lane], t0);
    arow[lane + 32] = f4add(arow[lane + 32], t1);
}

// ---------------- batchnorm ----------------
__global__ void k_bnstats(const float* __restrict__ acc, float* __restrict__ st) {
    int c = threadIdx.x;
    float s = 0.f, q = 0.f;
    for (int r = blockIdx.x; r < NN; r += gridDim.x) {
        float v = acc[(long long)r * HH + c];
        s += v;
        q += v * v;
    }
    atomicAdd(&st[c], s);
    atomicAdd(&st[HH + c], q);
}

__global__ void k_bnapply(const float* __restrict__ acc, float* __restrict__ x,
                          const float* __restrict__ st, const float* __restrict__ gamma,
                          const float* __restrict__ beta, int resid) {
    int c = threadIdx.x;
    float meanA = st[c] * (1.0f / NN);
    float varA  = st[HH + c] * (1.0f / NN) - meanA * meanA;
    float varX  = varA * (1.0f / 9.0f);                  // var of acc/3
    float rs    = rsqrtf(varX + 1e-5f);
    float scale = gamma[c] * rs * (1.0f / 3.0f);
    float shift = beta[c] - meanA * scale;
    for (int r = blockIdx.x; r < NN; r += gridDim.x) {
        long long i = (long long)r * HH + c;
        float y = fmaxf(fmaf(acc[i], scale, shift), 0.0f);
        x[i] = resid ? (x[i] + y) : y;
    }
}

// ---------------- pooling + head ----------------
__global__ void k_pcnt(const void* __restrict__ bv, const void* __restrict__ bp) {
    int is64 = g_is64;
    int gid = blockIdx.x * blockDim.x + threadIdx.x;
    if (gid >= 2 * NN) return;
    int t = gid / NN, i = gid - t * NN;
    int g = t ? idx_at(bp, i, is64) : idx_at(bv, i, is64);
    atomicAdd(&g_pcnt[t][g], 1);
}

__global__ void k_pool(const float* __restrict__ x, const void* __restrict__ batch,
                       float* __restrict__ pool) {
    int is64 = g_is64;
    int c = threadIdx.x;
    int r0 = blockIdx.x * 64;
    int r1 = min(r0 + 64, NN);
    float local = 0.f;
    int gprev = -1;
    for (int r = r0; r < r1; r++) {
        int g = idx_at(batch, r, is64);
        if (g != gprev) {
            if (gprev >= 0) atomicAdd(&pool[gprev * HH + c], local);
            local = 0.f;
            gprev = g;
        }
        local += x[(long long)r * HH + c];
    }
    if (gprev >= 0) atomicAdd(&pool[gprev * HH + c], local);
}

__global__ void k_final(const float* __restrict__ Wo, const float* __restrict__ bo,
                        float* __restrict__ out) {
    int g = threadIdx.x >> 5, lane = threadIdx.x & 31;
    if (g >= GG) return;
    float cv = (float)max(g_pcnt[0][g], 1);
    float cp = (float)max(g_pcnt[1][g], 1);
    float s = 0.f;
    for (int c = lane; c < HH; c += 32)
        s += g_pool[0][g * HH + c] / cv * Wo[c] + g_pool[1][g * HH + c] / cp * Wo[HH + c];
#pragma unroll
    for (int off = 16; off; off >>= 1) s += __shfl_down_sync(0xffffffffu, s, off);
    if (lane == 0) out[g] = 1.0f / (1.0f + expf(-(s + bo[0])));
}

// ---------------- launcher ----------------
extern "C" void kernel_launch(void* const* d_in, const int* in_sizes, int n_in,
                              void* d_out, int out_size) {
    const float* x_vuln  = (const float*)d_in[0];
    const float* x_patch = (const float*)d_in[1];
    const float* W_emb   = (const float*)d_in[2];
    const float* b_emb   = (const float*)d_in[3];
    const float* W_l     = (const float*)d_in[4];
    const float* b_l     = (const float*)d_in[5];
    const float* W_r     = (const float*)d_in[6];
    const float* gamma   = (const float*)d_in[7];
    const float* beta    = (const float*)d_in[8];
    const float* W_out   = (const float*)d_in[9];
    const float* b_out   = (const float*)d_in[10];
    const void* edge     = d_in[11];
    const void* batch_v  = d_in[12];
    const void* batch_p  = d_in[13];
    float* out = (float*)d_out;

    void* p;
    cudaGetSymbolAddress(&p, g_x);     float* x0 = (float*)p; float* x1 = x0 + (size_t)NN * HH;
    cudaGetSymbolAddress(&p, g_accb);  float* a0 = (float*)p; float* a1 = a0 + (size_t)NN * HH;
    cudaGetSymbolAddress(&p, g_tmp);   float* tmp = (float*)p;
    cudaGetSymbolAddress(&p, g_wrsum); float* wrs = (float*)p;
    cudaGetSymbolAddress(&p, g_blsum); float* bls = (float*)p;
    cudaGetSymbolAddress(&p, g_deg);   void* degp = p;
    cudaGetSymbolAddress(&p, g_stats); float* stats = (float*)p;
    cudaGetSymbolAddress(&p, g_pool);  float* pool = (float*)p;
    cudaGetSymbolAddress(&p, g_pcnt);  void* pcnt = p;

    // index dtype detection, then CSR build (edges constant across layers)
    k_detect<<<1, 256>>>((const unsigned int*)edge);
    cudaMemsetAsync(degp, 0, sizeof(int) * NREL * NN, 0);
    k_hist<<<(NREL * EE + 255) / 256, 256>>>(edge);
    k_scan<<<NREL, 1024>>>();
    k_fill<<<(NREL * EE + 255) / 256, 256>>>(edge);

    dim3 tgrid((NN + 127) / 128, 4, 1);
    // embedding: x[t] = x_in @ W_emb[t] + b_emb[t]
    sgemm_bias<<<tgrid, 256>>>(x_vuln,  W_emb,            x0, b_emb,      NN, DIN, 0, 0);
    sgemm_bias<<<tgrid, 256>>>(x_patch, W_emb + DIN * HH, x1, b_emb + HH, NN, DIN, 0, 0);

    for (int layer = 0; layer < LL; layer++) {
        k_wsum<<<(2 * HH * HH + 255) / 256, 256>>>(W_r, b_l, layer);
        // self path: acc[t] = x[t] @ sum(W_r group) + sum(b_l group)
        sgemm_bias<<<tgrid, 256>>>(x0, wrs,           a0, bls,      NN, HH, 0, 0);
        sgemm_bias<<<tgrid, 256>>>(x1, wrs + HH * HH, a1, bls + HH, NN, HH, 0, 0);
        // neighbor path GEMMs: tmp[r] = x[st(r)] @ W_l[layer,r]
        dim3 zgrid((NN + 127) / 128, 4, 3);
        const float* Wlb = W_l + (size_t)layer * NREL * HH * HH;
        sgemm_bias<<<zgrid, 256>>>(x0, Wlb,               tmp,                       nullptr,
                                   NN, HH, (long long)HH * HH, (long long)NN * HH);
        sgemm_bias<<<zgrid, 256>>>(x1, Wlb + 3 * HH * HH, tmp + 3LL * NN * HH,       nullptr,
                                   NN, HH, (long long)HH * HH, (long long)NN * HH);
        // gather-mean into acc
        int aggBlocks = (NN * 32 + 255) / 256;
        k_agg<<<aggBlocks, 256>>>(0, 1, 3, a0);
        k_agg<<<aggBlocks, 256>>>(2, 4, 5, a1);
        // batchnorm + relu (+ residual)
        cudaMemsetAsync(stats, 0, sizeof(float) * 2 * 2 * HH, 0);
        k_bnstats<<<128, 256>>>(a0, stats);
        k_bnstats<<<128, 256>>>(a1, stats + 2 * HH);
        k_bnapply<<<256, 256>>>(a0, x0, stats,          gamma + (layer * 2 + 0) * HH,
                                beta + (layer * 2 + 0) * HH, layer > 0);
        k_bnapply<<<256, 256>>>(a1, x1, stats + 2 * HH, gamma + (layer * 2 + 1) * HH,
                                beta + (layer * 2 + 1) * HH, layer > 0);
    }

    // pooling + head
    cudaMemsetAsync(pool, 0, sizeof(float) * 2 * GG * HH, 0);
    cudaMemsetAsync(pcnt, 0, sizeof(int) * 2 * GG, 0);
    k_pcnt<<<(2 * NN + 255) / 256, 256>>>(batch_v, batch_p);
    k_pool<<<(NN + 63) / 64, 256>>>(x0, batch_v, pool);
    k_pool<<<(NN + 63) / 64, 256>>>(x1, batch_p, pool + GG * HH);
    k_final<<<1, 1024>>>(W_out, b_out, out);
}

// round 6
// speedup vs baseline: 1.2889x; 1.2889x over previous
#include <cuda_runtime.h>
#include <cuda_bf16.h>
#include <math.h>
#include <stdint.h>

#define NN   20000
#define EE   320000
#define DIN  128
#define HH   256
#define LL   2
#define GG   32
#define NREL 6

// ---------------- device scratch ----------------
__device__ float g_x[2 * NN * HH];
__device__ float g_accb[2 * NN * HH];
__device__ float g_tmp[NREL * NN * HH];
__device__ __nv_bfloat16 g_xhi[2 * NN * HH], g_xlo[2 * NN * HH];
__device__ __nv_bfloat16 g_inhi[2 * NN * DIN], g_inlo[2 * NN * DIN];
__device__ __nv_bfloat16 g_we_hi[2 * HH * DIN], g_we_lo[2 * HH * DIN];   // [t][n][k]
__device__ __nv_bfloat16 g_wl_hi[LL * NREL * HH * HH], g_wl_lo[LL * NREL * HH * HH]; // [l*6+r][n][k]
__device__ __nv_bfloat16 g_ws_hi[LL * 2 * HH * HH], g_ws_lo[LL * 2 * HH * HH];       // [l*2+t][n][k]
__device__ float g_blsum[LL * 2 * HH];
__device__ int   g_deg[NREL][NN];
__device__ int   g_rowptr[NREL][NN + 1];
__device__ int   g_cursor[NREL][NN];
__device__ int   g_col[NREL][EE];
__device__ float g_stats[2][2 * HH];
__device__ float g_pool[2][GG * HH];
__device__ int   g_pcnt[2][GG];
__device__ int   g_is64;

// ---------------- helpers ----------------
__device__ __forceinline__ float4 f4add(float4 a, float4 b) {
    return make_float4(a.x + b.x, a.y + b.y, a.z + b.z, a.w + b.w);
}
__device__ __forceinline__ float4 f4fma(float4 a, float s, float4 c) {
    return make_float4(fmaf(a.x, s, c.x), fmaf(a.y, s, c.y),
                       fmaf(a.z, s, c.z), fmaf(a.w, s, c.w));
}
__device__ __forceinline__ int idx_at(const void* p, long long i, int is64) {
    return is64 ? (int)((const long long*)p)[i] : ((const int*)p)[i];
}
__device__ __forceinline__ uint32_t smem_u32(const void* p) {
    uint32_t a;
    asm("{ .reg .u64 t; cvta.to.shared.u64 t, %1; cvt.u32.u64 %0, t; }" : "=r"(a) : "l"(p));
    return a;
}
__device__ __forceinline__ void split2(float v, __nv_bfloat16* h, __nv_bfloat16* l) {
    __nv_bfloat16 hh = __float2bfloat16(v);
    *h = hh;
    *l = __float2bfloat16(v - __bfloat162float(hh));
}
__device__ __forceinline__ void ldm_x4(uint32_t* r, uint32_t addr) {
    asm volatile("ldmatrix.sync.aligned.m8n8.x4.shared.b16 {%0,%1,%2,%3}, [%4];"
                 : "=r"(r[0]), "=r"(r[1]), "=r"(r[2]), "=r"(r[3]) : "r"(addr));
}
__device__ __forceinline__ void mma_bf16(float* c, const uint32_t* a, const uint32_t* b) {
    asm volatile("mma.sync.aligned.m16n8k16.row.col.f32.bf16.bf16.f32 "
                 "{%0,%1,%2,%3}, {%4,%5,%6,%7}, {%8,%9}, {%0,%1,%2,%3};"
                 : "+f"(c[0]), "+f"(c[1]), "+f"(c[2]), "+f"(c[3])
                 : "r"(a[0]), "r"(a[1]), "r"(a[2]), "r"(a[3]), "r"(b[0]), "r"(b[1]));
}

// ---------------- index dtype detection ----------------
__global__ void k_detect(const unsigned int* __restrict__ e) {
    __shared__ int any;
    if (threadIdx.x == 0) any = 0;
    __syncthreads();
    unsigned int v = 0;
    for (int i = threadIdx.x; i < 2048; i += blockDim.x)
        v |= e[(long long)i * 1874 + 1];
    if (v) any = 1;
    __syncthreads();
    if (threadIdx.x == 0) g_is64 = any ? 0 : 1;
}

// ---------------- CSR construction ----------------
__global__ void k_hist(const void* __restrict__ edge) {
    int is64 = g_is64;
    int gid = blockIdx.x * blockDim.x + threadIdx.x;
    if (gid >= NREL * EE) return;
    int r = gid / EE, e = gid - r * EE;
    int dst = idx_at(edge, ((long long)r * 2 + 1) * EE + e, is64);
    atomicAdd(&g_deg[r][dst], 1);
}

__global__ void k_scan() {
    int r = blockIdx.x;
    __shared__ int sh[1024];
    __shared__ int carry;
    if (threadIdx.x == 0) carry = 0;
    __syncthreads();
    for (int base = 0; base < NN; base += 1024) {
        int i = base + threadIdx.x;
        int v = (i < NN) ? g_deg[r][i] : 0;
        sh[threadIdx.x] = v;
        __syncthreads();
        for (int off = 1; off < 1024; off <<= 1) {
            int t = (threadIdx.x >= off) ? sh[threadIdx.x - off] : 0;
            __syncthreads();
            sh[threadIdx.x] += t;
            __syncthreads();
        }
        int incl = sh[threadIdx.x];
        if (i < NN) {
            int ex = carry + incl - v;
            g_rowptr[r][i] = ex;
            g_cursor[r][i] = ex;
        }
        __syncthreads();
        if (threadIdx.x == 1023) carry += incl;
        __syncthreads();
    }
    if (threadIdx.x == 0) g_rowptr[r][NN] = carry;
}

__global__ void k_fill(const void* __restrict__ edge) {
    int is64 = g_is64;
    int gid = blockIdx.x * blockDim.x + threadIdx.x;
    if (gid >= NREL * EE) return;
    int r = gid / EE, e = gid - r * EE;
    int src = idx_at(edge, ((long long)r * 2 + 0) * EE + e, is64);
    int dst = idx_at(edge, ((long long)r * 2 + 1) * EE + e, is64);
    int slot = atomicAdd(&g_cursor[r][dst], 1);
    g_col[r][slot] = src;
}

// ---------------- input split ----------------
__global__ void k_split(const float* __restrict__ x, __nv_bfloat16* __restrict__ h,
                        __nv_bfloat16* __restrict__ l, int n) {
    int i = blockIdx.x * blockDim.x + threadIdx.x;
    if (i >= n) return;
    split2(x[i], &h[i], &l[i]);
}

// ---------------- weight prep: transpose to [n][k] + bf16 hi/lo split ----------------
__global__ void k_wprep(const float* __restrict__ We, const float* __restrict__ Wl,
                        const float* __restrict__ Wr, const float* __restrict__ bl) {
    int gid = blockIdx.x * blockDim.x + threadIdx.x;
    const int grp[2][3] = {{0, 1, 3}, {2, 4, 5}};
    if (gid < 2 * HH * DIN) {
        int t = gid >> 15, rem = gid & 32767, n = rem >> 7, k = rem & 127;
        float v = We[((long long)t * DIN + k) * HH + n];
        split2(v, &g_we_hi[t * HH * DIN + n * DIN + k], &g_we_lo[t * HH * DIN + n * DIN + k]);
    }
    if (gid < LL * NREL * HH * HH) {
        int lr = gid >> 16, rem = gid & 65535, k = rem >> 8, n = rem & 255;
        float v = Wl[(long long)lr * 65536 + k * HH + n];
        split2(v, &g_wl_hi[lr * 65536 + n * HH + k], &g_wl_lo[lr * 65536 + n * HH + k]);
    }
    if (gid < LL * 2 * HH * HH) {
        int lt = gid >> 16, rem = gid & 65535, k = rem >> 8, n = rem & 255;
        int layer = lt >> 1, t = lt & 1;
        const float* W = Wr + (long long)layer * NREL * 65536;
        float v = W[grp[t][0] * 65536 + k * HH + n] + W[grp[t][1] * 65536 + k * HH + n] +
                  W[grp[t][2] * 65536 + k * HH + n];
        split2(v, &g_ws_hi[lt * 65536 + n * HH + k], &g_ws_lo[lt * 65536 + n * HH + k]);
    }
    if (gid < LL * 2 * HH) {
        int lt = gid >> 8, c = gid & 255;
        int layer = lt >> 1, t = lt & 1;
        const float* b = bl + (long long)layer * NREL * HH;
        g_blsum[lt * HH + c] = b[grp[t][0] * HH + c] + b[grp[t][1] * HH + c] +
                               b[grp[t][2] * HH + c];
    }
}

// ---------------- HMMA GEMM: C[M,256] = A[M,K] @ W[K,256] via bf16x3 ----------------
// A: bf16 hi/lo [M][K] row-major. B: bf16 hi/lo [256][K] K-major (i.e. W^T rows).
// CTA tile 128x128, BK=32, 8 warps (4 in M x 2 in N), warp tile 32x64.
#define SPAD 40   // smem row stride in bf16 elems (conflict-free ldmatrix)

__global__ void __launch_bounds__(256, 1) k_gemm(
    const __nv_bfloat16* __restrict__ Ahi, const __nv_bfloat16* __restrict__ Alo,
    const __nv_bfloat16* __restrict__ Bhi0, const __nv_bfloat16* __restrict__ Blo0,
    float* __restrict__ C0, const float* __restrict__ bias,
    int M, int K, long long sB, long long sC,
    __nv_bfloat16* __restrict__ Ohi, __nv_bfloat16* __restrict__ Olo)
{
    __shared__ __nv_bfloat16 sAh[128 * SPAD], sAl[128 * SPAD];
    __shared__ __nv_bfloat16 sBh[128 * SPAD], sBl[128 * SPAD];
    const __nv_bfloat16* Bhi = Bhi0 + (long long)blockIdx.z * sB;
    const __nv_bfloat16* Blo = Blo0 + (long long)blockIdx.z * sB;
    float* C = C0 + (long long)blockIdx.z * sC;

    int tid = threadIdx.x, wid = tid >> 5, lane = tid & 31;
    long long bm = (long long)blockIdx.x * 128;
    int nb = blockIdx.y * 128;
    int wm = (wid & 3) * 32;      // warp M offset in tile
    int wn = (wid >> 2) * 64;     // warp N offset in tile

    float acc[2][8][4];
#pragma unroll
    for (int i = 0; i < 2; i++)
#pragma unroll
        for (int j = 0; j < 8; j++)
#pragma unroll
            for (int q = 0; q < 4; q++) acc[i][j][q] = 0.0f;

    uint32_t sAh_b = smem_u32(sAh), sAl_b = smem_u32(sAl);
    uint32_t sBh_b = smem_u32(sBh), sBl_b = smem_u32(sBl);

    // precompute ldmatrix lane addresses (byte offsets within tile)
    // A x4: tiles (r0-7,k0),(r8-15,k0),(r0-7,k8),(r8-15,k8)
    int a_row = (lane & 7) + ((lane >> 3) & 1) * 8;
    int a_col = (lane >> 4) * 8;
    // B x4 per ntile: rows n0..7, k tiles 0,8,16,24
    int b_row = lane & 7;
    int b_col = (lane >> 3) * 8;

    for (int kc = 0; kc < K; kc += 32) {
        // ---- load tiles to smem ----
#pragma unroll
        for (int i = tid; i < 512; i += 256) {
            int row = i >> 2, seg = (i & 3) << 3;
            uint4 vh = make_uint4(0, 0, 0, 0), vl = vh;
            if (bm + row < M) {
                long long g = (bm + row) * K + kc + seg;
                vh = *(const uint4*)(Ahi + g);
                vl = *(const uint4*)(Alo + g);
            }
            *(uint4*)(sAh + row * SPAD + seg) = vh;
            *(uint4*)(sAl + row * SPAD + seg) = vl;
            long long gb = (long long)(nb + row) * K + kc + seg;
            *(uint4*)(sBh + row * SPAD + seg) = *(const uint4*)(Bhi + gb);
            *(uint4*)(sBl + row * SPAD + seg) = *(const uint4*)(Blo + gb);
        }
        __syncthreads();

        // ---- B fragments for whole chunk: [nt][4] covers both k-steps ----
        uint32_t bh[8][4], bl[8][4];
#pragma unroll
        for (int nt = 0; nt < 8; nt++) {
            uint32_t off = (uint32_t)((wn + nt * 8 + b_row) * SPAD + b_col) * 2;
            ldm_x4(bh[nt], sBh_b + off);
            ldm_x4(bl[nt], sBl_b + off);
        }
        // ---- k-steps ----
#pragma unroll
        for (int ks = 0; ks < 2; ks++) {
            uint32_t ah[2][4], al[2][4];
#pragma unroll
            for (int mt = 0; mt < 2; mt++) {
                uint32_t off = (uint32_t)((wm + mt * 16 + a_row) * SPAD + ks * 16 + a_col) * 2;
                ldm_x4(ah[mt], sAh_b + off);
                ldm_x4(al[mt], sAl_b + off);
            }
#pragma unroll
            for (int mt = 0; mt < 2; mt++)
#pragma unroll
                for (int nt = 0; nt < 8; nt++) {
                    mma_bf16(acc[mt][nt], ah[mt], &bh[nt][ks * 2]);
                    mma_bf16(acc[mt][nt], ah[mt], &bl[nt][ks * 2]);
                    mma_bf16(acc[mt][nt], al[mt], &bh[nt][ks * 2]);
                }
        }
        __syncthreads();
    }

    // ---- epilogue ----
    int gidr = lane >> 2, tig = lane & 3;
#pragma unroll
    for (int mt = 0; mt < 2; mt++) {
        long long r0 = bm + wm + mt * 16 + gidr;
        long long r1 = r0 + 8;
#pragma unroll
        for (int nt = 0; nt < 8; nt++) {
            int col = nb + wn + nt * 8 + tig * 2;
            float b0 = 0.f, b1 = 0.f;
            if (bias) { b0 = bias[col]; b1 = bias[col + 1]; }
            if (r0 < M) {
                float v0 = acc[mt][nt][0] + b0, v1 = acc[mt][nt][1] + b1;
                *(float2*)&C[r0 * 256 + col] = make_float2(v0, v1);
                if (Ohi) {
                    split2(v0, &Ohi[r0 * 256 + col], &Olo[r0 * 256 + col]);
                    split2(v1, &Ohi[r0 * 256 + col + 1], &Olo[r0 * 256 + col + 1]);
                }
            }
            if (r1 < M) {
                float v2 = acc[mt][nt][2] + b0, v3 = acc[mt][nt][3] + b1;
                *(float2*)&C[r1 * 256 + col] = make_float2(v2, v3);
                if (Ohi) {
                    split2(v2, &Ohi[r1 * 256 + col], &Olo[r1 * 256 + col]);
                    split2(v3, &Ohi[r1 * 256 + col + 1], &Olo[r1 * 256 + col + 1]);
                }
            }
        }
    }
}

// ---------------- gather-mean aggregation ----------------
__global__ void k_agg(int r0, int r1, int r2, float* __restrict__ acc) {
    int w = (blockIdx.x * blockDim.x + threadIdx.x) >> 5;
    int lane = threadIdx.x & 31;
    if (w >= NN) return;
    float4 t0 = make_float4(0.f, 0.f, 0.f, 0.f), t1 = t0;
    int rel[3] = {r0, r1, r2};
#pragma unroll
    for (int q = 0; q < 3; q++) {
        int r = rel[q];
        int b = g_rowptr[r][w], e = g_rowptr[r][w + 1];
        float4 s0 = make_float4(0.f, 0.f, 0.f, 0.f), s1 = s0;
        const float4* base = (const float4*)(g_tmp + (long long)r * NN * HH);
        int j = b;
        for (; j + 1 < e; j += 2) {
            int sa = g_col[r][j], sb = g_col[r][j + 1];
            const float4* ra = base + (long long)sa * 64;
            const float4* rb = base + (long long)sb * 64;
            s0 = f4add(s0, f4add(ra[lane], rb[lane]));
            s1 = f4add(s1, f4add(ra[lane + 32], rb[lane + 32]));
        }
        if (j < e) {
            const float4* ra = base + (long long)g_col[r][j] * 64;
            s0 = f4add(s0, ra[lane]);
            s1 = f4add(s1, ra[lane + 32]);
        }
        float inv = (e > b) ? 1.0f / (float)(e - b) : 0.0f;
        t0 = f4fma(s0, inv, t0);
        t1 = f4fma(s1, inv, t1);
    }
    float4* arow = (float4*)(acc + (long long)w * HH);
    arow[lane] = f4add(arow[lane], t0);
    arow[lane + 32] = f4add(arow[lane + 32], t1);
}

// ---------------- batchnorm ----------------
__global__ void k_bnstats(const float* __restrict__ acc, float* __restrict__ st) {
    int c = threadIdx.x;
    float s = 0.f, q = 0.f;
    for (int r = blockIdx.x; r < NN; r += gridDim.x) {
        float v = acc[(long long)r * HH + c];
        s += v;
        q += v * v;
    }
    atomicAdd(&st[c], s);
    atomicAdd(&st[HH + c], q);
}

__global__ void k_bnapply(const float* __restrict__ acc, float* __restrict__ x,
                          __nv_bfloat16* __restrict__ xh, __nv_bfloat16* __restrict__ xl,
                          const float* __restrict__ st, const float* __restrict__ gamma,
                          const float* __restrict__ beta, int resid) {
    int c = threadIdx.x;
    float meanA = st[c] * (1.0f / NN);
    float varA  = st[HH + c] * (1.0f / NN) - meanA * meanA;
    float varX  = varA * (1.0f / 9.0f);
    float rs    = rsqrtf(varX + 1e-5f);
    float scale = gamma[c] * rs * (1.0f / 3.0f);
    float shift = beta[c] - meanA * scale;
    for (int r = blockIdx.x; r < NN; r += gridDim.x) {
        long long i = (long long)r * HH + c;
        float y = fmaxf(fmaf(acc[i], scale, shift), 0.0f);
        float xn = resid ? (x[i] + y) : y;
        x[i] = xn;
        split2(xn, &xh[i], &xl[i]);
    }
}

// ---------------- pooling + head ----------------
__global__ void k_pcnt(const void* __restrict__ bv, const void* __restrict__ bp) {
    int is64 = g_is64;
    int gid = blockIdx.x * blockDim.x + threadIdx.x;
    if (gid >= 2 * NN) return;
    int t = gid / NN, i = gid - t * NN;
    int g = t ? idx_at(bp, i, is64) : idx_at(bv, i, is64);
    atomicAdd(&g_pcnt[t][g], 1);
}

__global__ void k_pool(const float* __restrict__ x, const void* __restrict__ batch,
                       float* __restrict__ pool) {
    int is64 = g_is64;
    int c = threadIdx.x;
    int r0 = blockIdx.x * 64;
    int r1 = min(r0 + 64, NN);
    float local = 0.f;
    int gprev = -1;
    for (int r = r0; r < r1; r++) {
        int g = idx_at(batch, r, is64);
        if (g != gprev) {
            if (gprev >= 0) atomicAdd(&pool[gprev * HH + c], local);
            local = 0.f;
            gprev = g;
        }
        local += x[(long long)r * HH + c];
    }
    if (gprev >= 0) atomicAdd(&pool[gprev * HH + c], local);
}

__global__ void k_final(const float* __restrict__ Wo, const float* __restrict__ bo,
                        float* __restrict__ out) {
    int g = threadIdx.x >> 5, lane = threadIdx.x & 31;
    if (g >= GG) return;
    float cv = (float)max(g_pcnt[0][g], 1);
    float cp = (float)max(g_pcnt[1][g], 1);
    float s = 0.f;
    for (int c = lane; c < HH; c += 32)
        s += g_pool[0][g * HH + c] / cv * Wo[c] + g_pool[1][g * HH + c] / cp * Wo[HH + c];
#pragma unroll
    for (int off = 16; off; off >>= 1) s += __shfl_down_sync(0xffffffffu, s, off);
    if (lane == 0) out[g] = 1.0f / (1.0f + expf(-(s + bo[0])));
}

// ---------------- launcher ----------------
extern "C" void kernel_launch(void* const* d_in, const int* in_sizes, int n_in,
                              void* d_out, int out_size) {
    const float* x_vuln  = (const float*)d_in[0];
    const float* x_patch = (const float*)d_in[1];
    const float* W_emb   = (const float*)d_in[2];
    const float* b_emb   = (const float*)d_in[3];
    const float* W_l     = (const float*)d_in[4];
    const float* b_l     = (const float*)d_in[5];
    const float* W_r     = (const float*)d_in[6];
    const float* gamma   = (const float*)d_in[7];
    const float* beta    = (const float*)d_in[8];
    const float* W_out   = (const float*)d_in[9];
    const float* b_out   = (const float*)d_in[10];
    const void* edge     = d_in[11];
    const void* batch_v  = d_in[12];
    const void* batch_p  = d_in[13];
    float* out = (float*)d_out;

    void* p;
    cudaGetSymbolAddress(&p, g_x);     float* x0 = (float*)p;  float* x1 = x0 + (size_t)NN * HH;
    cudaGetSymbolAddress(&p, g_accb);  float* a0 = (float*)p;  float* a1 = a0 + (size_t)NN * HH;
    cudaGetSymbolAddress(&p, g_tmp);   float* tmp = (float*)p;
    cudaGetSymbolAddress(&p, g_xhi);   __nv_bfloat16* xhi = (__nv_bfloat16*)p;
    cudaGetSymbolAddress(&p, g_xlo);   __nv_bfloat16* xlo = (__nv_bfloat16*)p;
    cudaGetSymbolAddress(&p, g_inhi);  __nv_bfloat16* ihi = (__nv_bfloat16*)p;
    cudaGetSymbolAddress(&p, g_inlo);  __nv_bfloat16* ilo = (__nv_bfloat16*)p;
    cudaGetSymbolAddress(&p, g_we_hi); __nv_bfloat16* wehi = (__nv_bfloat16*)p;
    cudaGetSymbolAddress(&p, g_we_lo); __nv_bfloat16* welo = (__nv_bfloat16*)p;
    cudaGetSymbolAddress(&p, g_wl_hi); __nv_bfloat16* wlhi = (__nv_bfloat16*)p;
    cudaGetSymbolAddress(&p, g_wl_lo); __nv_bfloat16* wllo = (__nv_bfloat16*)p;
    cudaGetSymbolAddress(&p, g_ws_hi); __nv_bfloat16* wshi = (__nv_bfloat16*)p;
    cudaGetSymbolAddress(&p, g_ws_lo); __nv_bfloat16* wslo = (__nv_bfloat16*)p;
    cudaGetSymbolAddress(&p, g_blsum); float* bls = (float*)p;
    cudaGetSymbolAddress(&p, g_deg);   void* degp = p;
    cudaGetSymbolAddress(&p, g_stats); float* stats = (float*)p;
    cudaGetSymbolAddress(&p, g_pool);  float* pool = (float*)p;
    cudaGetSymbolAddress(&p, g_pcnt);  void* pcnt = p;

    // index dtype detection + CSR build
    k_detect<<<1, 256>>>((const unsigned int*)edge);
    cudaMemsetAsync(degp, 0, sizeof(int) * NREL * NN, 0);
    k_hist<<<(NREL * EE + 255) / 256, 256>>>(edge);
    k_scan<<<NREL, 1024>>>();
    k_fill<<<(NREL * EE + 255) / 256, 256>>>(edge);

    // weight prep + input split
    k_wprep<<<3072, 256>>>(W_emb, W_l, W_r, b_l);
    k_split<<<(NN * DIN + 255) / 256, 256>>>(x_vuln,  ihi,            ilo,            NN * DIN);
    k_split<<<(NN * DIN + 255) / 256, 256>>>(x_patch, ihi + NN * DIN, ilo + NN * DIN, NN * DIN);

    const int MB = (NN + 127) / 128;
    // embedding GEMMs (K=128), fused hi/lo split of outputs
    k_gemm<<<dim3(MB, 2, 1), 256>>>(ihi, ilo, wehi, welo, x0, b_emb,
                                    NN, DIN, 0, 0, xhi, xlo);
    k_gemm<<<dim3(MB, 2, 1), 256>>>(ihi + NN * DIN, ilo + NN * DIN,
                                    wehi + HH * DIN, welo + HH * DIN,
                                    x1, b_emb + HH, NN, DIN, 0, 0,
                                    xhi + (size_t)NN * HH, xlo + (size_t)NN * HH);

    for (int layer = 0; layer < LL; layer++) {
        size_t xs = (size_t)NN * HH;
        // self path
        k_gemm<<<dim3(MB, 2, 1), 256>>>(xhi, xlo,
            wshi + (size_t)(layer * 2 + 0) * HH * HH, wslo + (size_t)(layer * 2 + 0) * HH * HH,
            a0, bls + (layer * 2 + 0) * HH, NN, HH, 0, 0, nullptr, nullptr);
        k_gemm<<<dim3(MB, 2, 1), 256>>>(xhi + xs, xlo + xs,
            wshi + (size_t)(layer * 2 + 1) * HH * HH, wslo + (size_t)(layer * 2 + 1) * HH * HH,
            a1, bls + (layer * 2 + 1) * HH, NN, HH, 0, 0, nullptr, nullptr);
        // neighbor path: z-batched over the 3 relations per source type
        size_t wb = (size_t)layer * NREL * HH * HH;
        k_gemm<<<dim3(MB, 2, 3), 256>>>(xhi, xlo, wlhi + wb, wllo + wb,
            tmp, nullptr, NN, HH, (long long)HH * HH, (long long)NN * HH, nullptr, nullptr);
        k_gemm<<<dim3(MB, 2, 3), 256>>>(xhi + xs, xlo + xs,
            wlhi + wb + 3 * (size_t)HH * HH, wllo + wb + 3 * (size_t)HH * HH,
            tmp + 3 * (size_t)NN * HH, nullptr, NN, HH,
            (long long)HH * HH, (long long)NN * HH, nullptr, nullptr);
        // gather-mean
        int aggBlocks = (NN * 32 + 255) / 256;
        k_agg<<<aggBlocks, 256>>>(0, 1, 3, a0);
        k_agg<<<aggBlocks, 256>>>(2, 4, 5, a1);
        // batchnorm + relu (+ residual), fused hi/lo split
        cudaMemsetAsync(stats, 0, sizeof(float) * 2 * 2 * HH, 0);
        k_bnstats<<<128, 256>>>(a0, stats);
        k_bnstats<<<128, 256>>>(a1, stats + 2 * HH);
        k_bnapply<<<256, 256>>>(a0, x0, xhi, xlo, stats,
                                gamma + (layer * 2 + 0) * HH, beta + (layer * 2 + 0) * HH, layer > 0);
        k_bnapply<<<256, 256>>>(a1, x1, xhi + xs, xlo + xs, stats + 2 * HH,
                                gamma + (layer * 2 + 1) * HH, beta + (layer * 2 + 1) * HH, layer > 0);
    }

    // pooling + head
    cudaMemsetAsync(pool, 0, sizeof(float) * 2 * GG * HH, 0);
    cudaMemsetAsync(pcnt, 0, sizeof(int) * 2 * GG, 0);
    k_pcnt<<<(2 * NN + 255) / 256, 256>>>(batch_v, batch_p);
    k_pool<<<(NN + 63) / 64, 256>>>(x0, batch_v, pool);
    k_pool<<<(NN + 63) / 64, 256>>>(x1, batch_p, pool + GG * HH);
    k_final<<<1, 1024>>>(W_out, b_out, out);
}

// round 7
// speedup vs baseline: 1.4653x; 1.1369x over previous
#include <cuda_runtime.h>
#include <cuda_bf16.h>
#include <math.h>
#include <stdint.h>

#define NN   20000
#define EE   320000
#define DIN  128
#define HH   256
#define LL   2
#define GG   32
#define NREL 6

// ---------------- device scratch ----------------
__device__ float g_x[2 * NN * HH];
__device__ float g_accb[2 * NN * HH];
__device__ __nv_bfloat16 g_tmpb[NREL * NN * HH];   // neighbor GEMM outputs (bf16)
__device__ __nv_bfloat16 g_xhi[2 * NN * HH], g_xlo[2 * NN * HH];
__device__ __nv_bfloat16 g_inhi[2 * NN * DIN], g_inlo[2 * NN * DIN];
__device__ __nv_bfloat16 g_we_hi[2 * HH * DIN], g_we_lo[2 * HH * DIN];   // [t][n][k]
__device__ __nv_bfloat16 g_wl_hi[LL * NREL * HH * HH], g_wl_lo[LL * NREL * HH * HH]; // [l*6+r][n][k]
__device__ __nv_bfloat16 g_ws_hi[LL * 2 * HH * HH], g_ws_lo[LL * 2 * HH * HH];       // [l*2+t][n][k]
__device__ float g_blsum[LL * 2 * HH];
__device__ int   g_deg[NREL][NN];
__device__ int   g_rowptr[NREL][NN + 1];
__device__ int   g_cursor[NREL][NN];
__device__ int   g_col[NREL][EE];
__device__ float g_stats[2][2 * HH];
__device__ float g_pool[2][GG * HH];
__device__ int   g_pcnt[2][GG];
__device__ int   g_is64;

// ---------------- helpers ----------------
__device__ __forceinline__ int idx_at(const void* p, long long i, int is64) {
    return is64 ? (int)((const long long*)p)[i] : ((const int*)p)[i];
}
__device__ __forceinline__ uint32_t smem_u32(const void* p) {
    uint32_t a;
    asm("{ .reg .u64 t; cvta.to.shared.u64 t, %1; cvt.u32.u64 %0, t; }" : "=r"(a) : "l"(p));
    return a;
}
__device__ __forceinline__ void split2(float v, __nv_bfloat16* h, __nv_bfloat16* l) {
    __nv_bfloat16 hh = __float2bfloat16(v);
    *h = hh;
    *l = __float2bfloat16(v - __bfloat162float(hh));
}
__device__ __forceinline__ void ldm_x4(uint32_t* r, uint32_t addr) {
    asm volatile("ldmatrix.sync.aligned.m8n8.x4.shared.b16 {%0,%1,%2,%3}, [%4];"
                 : "=r"(r[0]), "=r"(r[1]), "=r"(r[2]), "=r"(r[3]) : "r"(addr));
}
__device__ __forceinline__ void mma_bf16(float* c, const uint32_t* a, const uint32_t* b) {
    asm volatile("mma.sync.aligned.m16n8k16.row.col.f32.bf16.bf16.f32 "
                 "{%0,%1,%2,%3}, {%4,%5,%6,%7}, {%8,%9}, {%0,%1,%2,%3};"
                 : "+f"(c[0]), "+f"(c[1]), "+f"(c[2]), "+f"(c[3])
                 : "r"(a[0]), "r"(a[1]), "r"(a[2]), "r"(a[3]), "r"(b[0]), "r"(b[1]));
}
__device__ __forceinline__ void cp16(uint32_t dst, const void* src, int nbytes) {
    asm volatile("cp.async.cg.shared.global [%0], [%1], 16, %2;"
                 :: "r"(dst), "l"(src), "r"(nbytes));
}

// ---------------- index dtype detection ----------------
__global__ void k_detect(const unsigned int* __restrict__ e) {
    __shared__ int any;
    if (threadIdx.x == 0) any = 0;
    __syncthreads();
    unsigned int v = 0;
    for (int i = threadIdx.x; i < 2048; i += blockDim.x)
        v |= e[(long long)i * 1874 + 1];
    if (v) any = 1;
    __syncthreads();
    if (threadIdx.x == 0) g_is64 = any ? 0 : 1;
}

// ---------------- CSR construction ----------------
__global__ void k_hist(const void* __restrict__ edge) {
    int is64 = g_is64;
    int gid = blockIdx.x * blockDim.x + threadIdx.x;
    if (gid >= NREL * EE) return;
    int r = gid / EE, e = gid - r * EE;
    int dst = idx_at(edge, ((long long)r * 2 + 1) * EE + e, is64);
    atomicAdd(&g_deg[r][dst], 1);
}

__global__ void k_scan() {
    int r = blockIdx.x;
    __shared__ int sh[1024];
    __shared__ int carry;
    if (threadIdx.x == 0) carry = 0;
    __syncthreads();
    for (int base = 0; base < NN; base += 1024) {
        int i = base + threadIdx.x;
        int v = (i < NN) ? g_deg[r][i] : 0;
        sh[threadIdx.x] = v;
        __syncthreads();
        for (int off = 1; off < 1024; off <<= 1) {
            int t = (threadIdx.x >= off) ? sh[threadIdx.x - off] : 0;
            __syncthreads();
            sh[threadIdx.x] += t;
            __syncthreads();
        }
        int incl = sh[threadIdx.x];
        if (i < NN) {
            int ex = carry + incl - v;
            g_rowptr[r][i] = ex;
            g_cursor[r][i] = ex;
        }
        __syncthreads();
        if (threadIdx.x == 1023) carry += incl;
        __syncthreads();
    }
    if (threadIdx.x == 0) g_rowptr[r][NN] = carry;
}

__global__ void k_fill(const void* __restrict__ edge) {
    int is64 = g_is64;
    int gid = blockIdx.x * blockDim.x + threadIdx.x;
    if (gid >= NREL * EE) return;
    int r = gid / EE, e = gid - r * EE;
    int src = idx_at(edge, ((long long)r * 2 + 0) * EE + e, is64);
    int dst = idx_at(edge, ((long long)r * 2 + 1) * EE + e, is64);
    int slot = atomicAdd(&g_cursor[r][dst], 1);
    g_col[r][slot] = src;
}

// ---------------- input split ----------------
__global__ void k_split(const float* __restrict__ x, __nv_bfloat16* __restrict__ h,
                        __nv_bfloat16* __restrict__ l, int n) {
    int i = blockIdx.x * blockDim.x + threadIdx.x;
    if (i >= n) return;
    split2(x[i], &h[i], &l[i]);
}

// ---------------- weight prep: transpose to [n][k] + bf16 hi/lo split ----------------
__global__ void k_wprep(const float* __restrict__ We, const float* __restrict__ Wl,
                        const float* __restrict__ Wr, const float* __restrict__ bl) {
    int gid = blockIdx.x * blockDim.x + threadIdx.x;
    const int grp[2][3] = {{0, 1, 3}, {2, 4, 5}};
    if (gid < 2 * HH * DIN) {
        int t = gid >> 15, rem = gid & 32767, n = rem >> 7, k = rem & 127;
        float v = We[((long long)t * DIN + k) * HH + n];
        split2(v, &g_we_hi[t * HH * DIN + n * DIN + k], &g_we_lo[t * HH * DIN + n * DIN + k]);
    }
    if (gid < LL * NREL * HH * HH) {
        int lr = gid >> 16, rem = gid & 65535, k = rem >> 8, n = rem & 255;
        float v = Wl[(long long)lr * 65536 + k * HH + n];
        split2(v, &g_wl_hi[lr * 65536 + n * HH + k], &g_wl_lo[lr * 65536 + n * HH + k]);
    }
    if (gid < LL * 2 * HH * HH) {
        int lt = gid >> 16, rem = gid & 65535, k = rem >> 8, n = rem & 255;
        int layer = lt >> 1, t = lt & 1;
        const float* W = Wr + (long long)layer * NREL * 65536;
        float v = W[grp[t][0] * 65536 + k * HH + n] + W[grp[t][1] * 65536 + k * HH + n] +
                  W[grp[t][2] * 65536 + k * HH + n];
        split2(v, &g_ws_hi[lt * 65536 + n * HH + k], &g_ws_lo[lt * 65536 + n * HH + k]);
    }
    if (gid < LL * 2 * HH) {
        int lt = gid >> 8, c = gid & 255;
        int layer = lt >> 1, t = lt & 1;
        const float* b = bl + (long long)layer * NREL * HH;
        g_blsum[lt * HH + c] = b[grp[t][0] * HH + c] + b[grp[t][1] * HH + c] +
                               b[grp[t][2] * HH + c];
    }
}

// ---------------- HMMA GEMM (cp.async double-buffered): C[M,256] = A[M,K] @ W[K,256] ----------------
// A: bf16 hi/lo [M][K] row-major. B: bf16 hi/lo [256][K] K-major.
// bf16x3: D += Ahi*Bhi + Ahi*Blo + Alo*Bhi (fp32 acc).
// CTA tile 128x128, BK=32, 8 warps (4M x 2N), warp tile 32x64, 2-stage cp.async pipeline.
#define SPAD 40
#define ARRB (128 * SPAD * 2)   // bytes per smem array (10240)
#define SMEM_TOT (2 * 4 * ARRB) // 81920

__global__ void __launch_bounds__(256) k_gemm(
    const __nv_bfloat16* __restrict__ Ahi, const __nv_bfloat16* __restrict__ Alo,
    const __nv_bfloat16* __restrict__ Bhi0, const __nv_bfloat16* __restrict__ Blo0,
    float* __restrict__ C0, const float* __restrict__ bias,
    int M, int K, long long sB, long long sC,
    __nv_bfloat16* __restrict__ Ohi, __nv_bfloat16* __restrict__ Olo,
    __nv_bfloat16* __restrict__ Cb0)
{
    extern __shared__ __nv_bfloat16 sm[];
    const __nv_bfloat16* Bhi = Bhi0 + (long long)blockIdx.z * sB;
    const __nv_bfloat16* Blo = Blo0 + (long long)blockIdx.z * sB;

    int tid = threadIdx.x, wid = tid >> 5, lane = tid & 31;
    long long bm = (long long)blockIdx.x * 128;
    int nb = blockIdx.y * 128;
    int wm = (wid & 3) * 32;
    int wn = (wid >> 2) * 64;
    uint32_t sb = smem_u32(sm);

    float acc[2][8][4];
#pragma unroll
    for (int i = 0; i < 2; i++)
#pragma unroll
        for (int j = 0; j < 8; j++)
#pragma unroll
            for (int q = 0; q < 4; q++) acc[i][j][q] = 0.0f;

    int a_row = (lane & 7) + ((lane >> 3) & 1) * 8;
    int a_col = (lane >> 4) * 8;
    int b_row = lane & 7;
    int b_col = (lane >> 3) * 8;

    int nch = K >> 5;

    // stage loader: 512 (row,seg) pairs over 256 threads, 4 arrays each
#define ISSUE_STAGE(c, buf) do {                                                  \
        uint32_t base = sb + (buf) * 4 * ARRB;                                    \
        _Pragma("unroll")                                                         \
        for (int i = tid; i < 512; i += 256) {                                    \
            int row = i >> 2, seg = (i & 3) << 3;                                 \
            uint32_t so = (uint32_t)(row * SPAD + seg) * 2;                       \
            int av = (bm + row < M) ? 16 : 0;                                     \
            long long ga = (bm + row < M) ? ((bm + row) * K + (c) * 32 + seg) : 0;\
            long long gb = (long long)(nb + row) * K + (c) * 32 + seg;           \
            cp16(base + so,            Ahi + ga, av);                             \
            cp16(base + ARRB + so,     Alo + ga, av);                             \
            cp16(base + 2 * ARRB + so, Bhi + gb, 16);                             \
            cp16(base + 3 * ARRB + so, Blo + gb, 16);                             \
        }                                                                         \
        asm volatile("cp.async.commit_group;");                                   \
    } while (0)

    ISSUE_STAGE(0, 0);

    for (int c = 0; c < nch; c++) {
        if (c + 1 < nch) {
            ISSUE_STAGE(c + 1, (c + 1) & 1);
            asm volatile("cp.async.wait_group 1;");
        } else {
            asm volatile("cp.async.wait_group 0;");
        }
        __syncthreads();

        uint32_t bs = sb + (c & 1) * 4 * ARRB;
        uint32_t sAh_b = bs, sAl_b = bs + ARRB, sBh_b = bs + 2 * ARRB, sBl_b = bs + 3 * ARRB;

        uint32_t bh[8][4], bl[8][4];
#pragma unroll
        for (int nt = 0; nt < 8; nt++) {
            uint32_t off = (uint32_t)((wn + nt * 8 + b_row) * SPAD + b_col) * 2;
            ldm_x4(bh[nt], sBh_b + off);
            ldm_x4(bl[nt], sBl_b + off);
        }
#pragma unroll
        for (int ks = 0; ks < 2; ks++) {
            uint32_t ah[2][4], al[2][4];
#pragma unroll
            for (int mt = 0; mt < 2; mt++) {
                uint32_t off = (uint32_t)((wm + mt * 16 + a_row) * SPAD + ks * 16 + a_col) * 2;
                ldm_x4(ah[mt], sAh_b + off);
                ldm_x4(al[mt], sAl_b + off);
            }
#pragma unroll
            for (int mt = 0; mt < 2; mt++)
#pragma unroll
                for (int nt = 0; nt < 8; nt++) {
                    mma_bf16(acc[mt][nt], ah[mt], &bh[nt][ks * 2]);
                    mma_bf16(acc[mt][nt], ah[mt], &bl[nt][ks * 2]);
                    mma_bf16(acc[mt][nt], al[mt], &bh[nt][ks * 2]);
                }
        }
        __syncthreads();
    }
#undef ISSUE_STAGE

    // ---- epilogue ----
    float* C = C0 ? C0 + (long long)blockIdx.z * sC : nullptr;
    __nv_bfloat16* Cb = Cb0 ? Cb0 + (long long)blockIdx.z * sC : nullptr;
    int gidr = lane >> 2, tig = lane & 3;
#pragma unroll
    for (int mt = 0; mt < 2; mt++) {
        long long r0 = bm + wm + mt * 16 + gidr;
        long long r1 = r0 + 8;
#pragma unroll
        for (int nt = 0; nt < 8; nt++) {
            int col = nb + wn + nt * 8 + tig * 2;
            float b0 = 0.f, b1 = 0.f;
            if (bias) { b0 = bias[col]; b1 = bias[col + 1]; }
            if (r0 < M) {
                float v0 = acc[mt][nt][0] + b0, v1 = acc[mt][nt][1] + b1;
                if (Cb) {
                    *(__nv_bfloat162*)&Cb[r0 * 256 + col] = __floats2bfloat162_rn(v0, v1);
                } else {
                    *(float2*)&C[r0 * 256 + col] = make_float2(v0, v1);
                    if (Ohi) {
                        split2(v0, &Ohi[r0 * 256 + col], &Olo[r0 * 256 + col]);
                        split2(v1, &Ohi[r0 * 256 + col + 1], &Olo[r0 * 256 + col + 1]);
                    }
                }
            }
            if (r1 < M) {
                float v2 = acc[mt][nt][2] + b0, v3 = acc[mt][nt][3] + b1;
                if (Cb) {
                    *(__nv_bfloat162*)&Cb[r1 * 256 + col] = __floats2bfloat162_rn(v2, v3);
                } else {
                    *(float2*)&C[r1 * 256 + col] = make_float2(v2, v3);
                    if (Ohi) {
                        split2(v2, &Ohi[r1 * 256 + col], &Olo[r1 * 256 + col]);
                        split2(v3, &Ohi[r1 * 256 + col + 1], &Olo[r1 * 256 + col + 1]);
                    }
                }
            }
        }
    }
}

// ---------------- gather-mean aggregation (bf16 source, fp32 accumulate) ----------------
__global__ void k_agg(int r0, int r1, int r2, float* __restrict__ acc) {
    int w = (blockIdx.x * blockDim.x + threadIdx.x) >> 5;
    int lane = threadIdx.x & 31;
    if (w >= NN) return;
    float t[8] = {0.f, 0.f, 0.f, 0.f, 0.f, 0.f, 0.f, 0.f};
    int rel[3] = {r0, r1, r2};
#pragma unroll
    for (int q = 0; q < 3; q++) {
        int r = rel[q];
        int b = g_rowptr[r][w], e = g_rowptr[r][w + 1];
        float s[8] = {0.f, 0.f, 0.f, 0.f, 0.f, 0.f, 0.f, 0.f};
        const uint4* base = (const uint4*)(g_tmpb + (long long)r * NN * HH);
        int j = b;
        for (; j + 1 < e; j += 2) {
            uint4 va = base[(long long)g_col[r][j] * 32 + lane];
            uint4 vb = base[(long long)g_col[r][j + 1] * 32 + lane];
            const __nv_bfloat162* ha = (const __nv_bfloat162*)&va;
            const __nv_bfloat162* hb = (const __nv_bfloat162*)&vb;
#pragma unroll
            for (int u = 0; u < 4; u++) {
                float2 fa = __bfloat1622float2(ha[u]);
                float2 fb = __bfloat1622float2(hb[u]);
                s[2 * u] += fa.x + fb.x;
                s[2 * u + 1] += fa.y + fb.y;
            }
        }
        if (j < e) {
            uint4 va = base[(long long)g_col[r][j] * 32 + lane];
            const __nv_bfloat162* ha = (const __nv_bfloat162*)&va;
#pragma unroll
            for (int u = 0; u < 4; u++) {
                float2 fa = __bfloat1622float2(ha[u]);
                s[2 * u] += fa.x;
                s[2 * u + 1] += fa.y;
            }
        }
        float inv = (e > b) ? 1.0f / (float)(e - b) : 0.0f;
#pragma unroll
        for (int u = 0; u < 8; u++) t[u] = fmaf(s[u], inv, t[u]);
    }
    float4* arow = (float4*)(acc + (long long)w * HH + lane * 8);
    float4 o0 = arow[0], o1 = arow[1];
    arow[0] = make_float4(o0.x + t[0], o0.y + t[1], o0.z + t[2], o0.w + t[3]);
    arow[1] = make_float4(o1.x + t[4], o1.y + t[5], o1.z + t[6], o1.w + t[7]);
}

// ---------------- batchnorm ----------------
__global__ void k_bnstats(const float* __restrict__ acc, float* __restrict__ st) {
    int c = threadIdx.x;
    float s = 0.f, q = 0.f;
    for (int r = blockIdx.x; r < NN; r += gridDim.x) {
        float v = acc[(long long)r * HH + c];
        s += v;
        q += v * v;
    }
    atomicAdd(&st[c], s);
    atomicAdd(&st[HH + c], q);
}

__global__ void k_bnapply(const float* __restrict__ acc, float* __restrict__ x,
                          __nv_bfloat16* __restrict__ xh, __nv_bfloat16* __restrict__ xl,
                          const float* __restrict__ st, const float* __restrict__ gamma,
                          const float* __restrict__ beta, int resid) {
    int c = threadIdx.x;
    float meanA = st[c] * (1.0f / NN);
    float varA  = st[HH + c] * (1.0f / NN) - meanA * meanA;
    float varX  = varA * (1.0f / 9.0f);
    float rs    = rsqrtf(varX + 1e-5f);
    float scale = gamma[c] * rs * (1.0f / 3.0f);
    float shift = beta[c] - meanA * scale;
    for (int r = blockIdx.x; r < NN; r += gridDim.x) {
        long long i = (long long)r * HH + c;
        float y = fmaxf(fmaf(acc[i], scale, shift), 0.0f);
        float xn = resid ? (x[i] + y) : y;
        x[i] = xn;
        split2(xn, &xh[i], &xl[i]);
    }
}

// ---------------- pooling + head ----------------
__global__ void k_pcnt(const void* __restrict__ bv, const void* __restrict__ bp) {
    int is64 = g_is64;
    int gid = blockIdx.x * blockDim.x + threadIdx.x;
    if (gid >= 2 * NN) return;
    int t = gid / NN, i = gid - t * NN;
    int g = t ? idx_at(bp, i, is64) : idx_at(bv, i, is64);
    atomicAdd(&g_pcnt[t][g], 1);
}

__global__ void k_pool(const float* __restrict__ x, const void* __restrict__ batch,
                       float* __restrict__ pool) {
    int is64 = g_is64;
    int c = threadIdx.x;
    int r0 = blockIdx.x * 64;
    int r1 = min(r0 + 64, NN);
    float local = 0.f;
    int gprev = -1;
    for (int r = r0; r < r1; r++) {
        int g = idx_at(batch, r, is64);
        if (g != gprev) {
            if (gprev >= 0) atomicAdd(&pool[gprev * HH + c], local);
            local = 0.f;
            gprev = g;
        }
        local += x[(long long)r * HH + c];
    }
    if (gprev >= 0) atomicAdd(&pool[gprev * HH + c], local);
}

__global__ void k_final(const float* __restrict__ Wo, const float* __restrict__ bo,
                        float* __restrict__ out) {
    int g = threadIdx.x >> 5, lane = threadIdx.x & 31;
    if (g >= GG) return;
    float cv = (float)max(g_pcnt[0][g], 1);
    float cp = (float)max(g_pcnt[1][g], 1);
    float s = 0.f;
    for (int c = lane; c < HH; c += 32)
        s += g_pool[0][g * HH + c] / cv * Wo[c] + g_pool[1][g * HH + c] / cp * Wo[HH + c];
#pragma unroll
    for (int off = 16; off; off >>= 1) s += __shfl_down_sync(0xffffffffu, s, off);
    if (lane == 0) out[g] = 1.0f / (1.0f + expf(-(s + bo[0])));
}

// ---------------- launcher ----------------
extern "C" void kernel_launch(void* const* d_in, const int* in_sizes, int n_in,
                              void* d_out, int out_size) {
    const float* x_vuln  = (const float*)d_in[0];
    const float* x_patch = (const float*)d_in[1];
    const float* W_emb   = (const float*)d_in[2];
    const float* b_emb   = (const float*)d_in[3];
    const float* W_l     = (const float*)d_in[4];
    const float* b_l     = (const float*)d_in[5];
    const float* W_r     = (const float*)d_in[6];
    const float* gamma   = (const float*)d_in[7];
    const float* beta    = (const float*)d_in[8];
    const float* W_out   = (const float*)d_in[9];
    const float* b_out   = (const float*)d_in[10];
    const void* edge     = d_in[11];
    const void* batch_v  = d_in[12];
    const void* batch_p  = d_in[13];
    float* out = (float*)d_out;

    void* p;
    cudaGetSymbolAddress(&p, g_x);     float* x0 = (float*)p;  float* x1 = x0 + (size_t)NN * HH;
    cudaGetSymbolAddress(&p, g_accb);  float* a0 = (float*)p;  float* a1 = a0 + (size_t)NN * HH;
    cudaGetSymbolAddress(&p, g_tmpb);  __nv_bfloat16* tmpb = (__nv_bfloat16*)p;
    cudaGetSymbolAddress(&p, g_xhi);   __nv_bfloat16* xhi = (__nv_bfloat16*)p;
    cudaGetSymbolAddress(&p, g_xlo);   __nv_bfloat16* xlo = (__nv_bfloat16*)p;
    cudaGetSymbolAddress(&p, g_inhi);  __nv_bfloat16* ihi = (__nv_bfloat16*)p;
    cudaGetSymbolAddress(&p, g_inlo);  __nv_bfloat16* ilo = (__nv_bfloat16*)p;
    cudaGetSymbolAddress(&p, g_we_hi); __nv_bfloat16* wehi = (__nv_bfloat16*)p;
    cudaGetSymbolAddress(&p, g_we_lo); __nv_bfloat16* welo = (__nv_bfloat16*)p;
    cudaGetSymbolAddress(&p, g_wl_hi); __nv_bfloat16* wlhi = (__nv_bfloat16*)p;
    cudaGetSymbolAddress(&p, g_wl_lo); __nv_bfloat16* wllo = (__nv_bfloat16*)p;
    cudaGetSymbolAddress(&p, g_ws_hi); __nv_bfloat16* wshi = (__nv_bfloat16*)p;
    cudaGetSymbolAddress(&p, g_ws_lo); __nv_bfloat16* wslo = (__nv_bfloat16*)p;
    cudaGetSymbolAddress(&p, g_blsum); float* bls = (float*)p;
    cudaGetSymbolAddress(&p, g_deg);   void* degp = p;
    cudaGetSymbolAddress(&p, g_stats); float* stats = (float*)p;
    cudaGetSymbolAddress(&p, g_pool);  float* pool = (float*)p;
    cudaGetSymbolAddress(&p, g_pcnt);  void* pcnt = p;

    cudaFuncSetAttribute(k_gemm, cudaFuncAttributeMaxDynamicSharedMemorySize, SMEM_TOT);

    // index dtype detection + CSR build
    k_detect<<<1, 256>>>((const unsigned int*)edge);
    cudaMemsetAsync(degp, 0, sizeof(int) * NREL * NN, 0);
    k_hist<<<(NREL * EE + 255) / 256, 256>>>(edge);
    k_scan<<<NREL, 1024>>>();
    k_fill<<<(NREL * EE + 255) / 256, 256>>>(edge);

    // weight prep + input split
    k_wprep<<<3072, 256>>>(W_emb, W_l, W_r, b_l);
    k_split<<<(NN * DIN + 255) / 256, 256>>>(x_vuln,  ihi,            ilo,            NN * DIN);
    k_split<<<(NN * DIN + 255) / 256, 256>>>(x_patch, ihi + NN * DIN, ilo + NN * DIN, NN * DIN);

    const int MB = (NN + 127) / 128;
    // embedding GEMMs (K=128), fused hi/lo split of outputs
    k_gemm<<<dim3(MB, 2, 1), 256, SMEM_TOT>>>(ihi, ilo, wehi, welo, x0, b_emb,
                                              NN, DIN, 0, 0, xhi, xlo, nullptr);
    k_gemm<<<dim3(MB, 2, 1), 256, SMEM_TOT>>>(ihi + NN * DIN, ilo + NN * DIN,
                                              wehi + HH * DIN, welo + HH * DIN,
                                              x1, b_emb + HH, NN, DIN, 0, 0,
                                              xhi + (size_t)NN * HH, xlo + (size_t)NN * HH, nullptr);

    for (int layer = 0; layer < LL; layer++) {
        size_t xs = (size_t)NN * HH;
        // self path (fp32 out into acc)
        k_gemm<<<dim3(MB, 2, 1), 256, SMEM_TOT>>>(xhi, xlo,
            wshi + (size_t)(layer * 2 + 0) * HH * HH, wslo + (size_t)(layer * 2 + 0) * HH * HH,
            a0, bls + (layer * 2 + 0) * HH, NN, HH, 0, 0, nullptr, nullptr, nullptr);
        k_gemm<<<dim3(MB, 2, 1), 256, SMEM_TOT>>>(xhi + xs, xlo + xs,
            wshi + (size_t)(layer * 2 + 1) * HH * HH, wslo + (size_t)(layer * 2 + 1) * HH * HH,
            a1, bls + (layer * 2 + 1) * HH, NN, HH, 0, 0, nullptr, nullptr, nullptr);
        // neighbor path: bf16 out into tmpb, z-batched over 3 relations per source type
        size_t wb = (size_t)layer * NREL * HH * HH;
        k_gemm<<<dim3(MB, 2, 3), 256, SMEM_TOT>>>(xhi, xlo, wlhi + wb, wllo + wb,
            nullptr, nullptr, NN, HH, (long long)HH * HH, (long long)NN * HH,
            nullptr, nullptr, tmpb);
        k_gemm<<<dim3(MB, 2, 3), 256, SMEM_TOT>>>(xhi + xs, xlo + xs,
            wlhi + wb + 3 * (size_t)HH * HH, wllo + wb + 3 * (size_t)HH * HH,
            nullptr, nullptr, NN, HH, (long long)HH * HH, (long long)NN * HH,
            nullptr, nullptr, tmpb + 3 * (size_t)NN * HH);
        // gather-mean
        int aggBlocks = (NN * 32 + 255) / 256;
        k_agg<<<aggBlocks, 256>>>(0, 1, 3, a0);
        k_agg<<<aggBlocks, 256>>>(2, 4, 5, a1);
        // batchnorm + relu (+ residual), fused hi/lo split
        cudaMemsetAsync(stats, 0, sizeof(float) * 2 * 2 * HH, 0);
        k_bnstats<<<128, 256>>>(a0, stats);
        k_bnstats<<<128, 256>>>(a1, stats + 2 * HH);
        k_bnapply<<<256, 256>>>(a0, x0, xhi, xlo, stats,
                                gamma + (layer * 2 + 0) * HH, beta + (layer * 2 + 0) * HH, layer > 0);
        k_bnapply<<<256, 256>>>(a1, x1, xhi + xs, xlo + xs, stats + 2 * HH,
                                gamma + (layer * 2 + 1) * HH, beta + (layer * 2 + 1) * HH, layer > 0);
    }

    // pooling + head
    cudaMemsetAsync(pool, 0, sizeof(float) * 2 * GG * HH, 0);
    cudaMemsetAsync(pcnt, 0, sizeof(int) * 2 * GG, 0);
    k_pcnt<<<(2 * NN + 255) / 256, 256>>>(batch_v, batch_p);
    k_pool<<<(NN + 63) / 64, 256>>>(x0, batch_v, pool);
    k_pool<<<(NN + 63) / 64, 256>>>(x1, batch_p, pool + GG * HH);
    k_final<<<1, 1024>>>(W_out, b_out, out);
}

// round 8
// speedup vs baseline: 2.1729x; 1.4829x over previous
#include <cuda_runtime.h>
#include <cuda_bf16.h>
#include <math.h>
#include <stdint.h>

#define NN   20000
#define EE   320000
#define DIN  128
#define HH   256
#define LL   2
#define GG   32
#define NREL 6

// ---------------- device scratch ----------------
__device__ float g_x[2 * NN * HH];
__device__ float g_accb[2 * NN * HH];
__device__ __nv_bfloat16 g_tmpb[NREL * NN * HH];     // neighbor GEMM outputs (bf16)
__device__ __nv_bfloat16 g_xb[2 * NN * HH];          // bf16 copy of x (GEMM A input)
__device__ __nv_bfloat16 g_inb[2 * NN * DIN];        // bf16 copy of raw inputs
__device__ __nv_bfloat16 g_web[2 * HH * DIN];        // emb weights [t][n][k]
__device__ __nv_bfloat16 g_wcat[LL * 2 * 1024 * HH]; // merged [l][t][1024 rows][k]: self(256) + 3 rel
__device__ float g_blsum[LL * 2 * HH];
__device__ int   g_deg[NREL][NN];
__device__ int   g_rowptr[NREL][NN + 1];
__device__ int   g_cursor[NREL][NN];
__device__ int   g_col[NREL][EE];
__device__ float g_stats[2][2 * HH];
__device__ float g_pool[2][GG * HH];
__device__ int   g_pcnt[2][GG];
__device__ int   g_is64;

// ---------------- helpers ----------------
__device__ __forceinline__ int idx_at(const void* p, long long i, int is64) {
    return is64 ? (int)((const long long*)p)[i] : ((const int*)p)[i];
}
__device__ __forceinline__ uint32_t smem_u32(const void* p) {
    uint32_t a;
    asm("{ .reg .u64 t; cvta.to.shared.u64 t, %1; cvt.u32.u64 %0, t; }" : "=r"(a) : "l"(p));
    return a;
}
__device__ __forceinline__ void ldm_x4(uint32_t* r, uint32_t addr) {
    asm volatile("ldmatrix.sync.aligned.m8n8.x4.shared.b16 {%0,%1,%2,%3}, [%4];"
                 : "=r"(r[0]), "=r"(r[1]), "=r"(r[2]), "=r"(r[3]) : "r"(addr));
}
__device__ __forceinline__ void mma_bf16(float* c, const uint32_t* a, const uint32_t* b) {
    asm volatile("mma.sync.aligned.m16n8k16.row.col.f32.bf16.bf16.f32 "
                 "{%0,%1,%2,%3}, {%4,%5,%6,%7}, {%8,%9}, {%0,%1,%2,%3};"
                 : "+f"(c[0]), "+f"(c[1]), "+f"(c[2]), "+f"(c[3])
                 : "r"(a[0]), "r"(a[1]), "r"(a[2]), "r"(a[3]), "r"(b[0]), "r"(b[1]));
}
__device__ __forceinline__ void cp16(uint32_t dst, const void* src, int nbytes) {
    asm volatile("cp.async.cg.shared.global [%0], [%1], 16, %2;"
                 :: "r"(dst), "l"(src), "r"(nbytes));
}

// ---------------- index dtype detection ----------------
__global__ void k_detect(const unsigned int* __restrict__ e) {
    __shared__ int any;
    if (threadIdx.x == 0) any = 0;
    __syncthreads();
    unsigned int v = 0;
    for (int i = threadIdx.x; i < 2048; i += blockDim.x)
        v |= e[(long long)i * 1874 + 1];
    if (v) any = 1;
    __syncthreads();
    if (threadIdx.x == 0) g_is64 = any ? 0 : 1;
}

// ---------------- CSR construction ----------------
__global__ void k_hist(const void* __restrict__ edge) {
    int is64 = g_is64;
    int gid = blockIdx.x * blockDim.x + threadIdx.x;
    if (gid >= NREL * EE) return;
    int r = gid / EE, e = gid - r * EE;
    int dst = idx_at(edge, ((long long)r * 2 + 1) * EE + e, is64);
    atomicAdd(&g_deg[r][dst], 1);
}

__global__ void k_scan() {
    int r = blockIdx.x;
    __shared__ int sh[1024];
    __shared__ int carry;
    if (threadIdx.x == 0) carry = 0;
    __syncthreads();
    for (int base = 0; base < NN; base += 1024) {
        int i = base + threadIdx.x;
        int v = (i < NN) ? g_deg[r][i] : 0;
        sh[threadIdx.x] = v;
        __syncthreads();
        for (int off = 1; off < 1024; off <<= 1) {
            int t = (threadIdx.x >= off) ? sh[threadIdx.x - off] : 0;
            __syncthreads();
            sh[threadIdx.x] += t;
            __syncthreads();
        }
        int incl = sh[threadIdx.x];
        if (i < NN) {
            int ex = carry + incl - v;
            g_rowptr[r][i] = ex;
            g_cursor[r][i] = ex;
        }
        __syncthreads();
        if (threadIdx.x == 1023) carry += incl;
        __syncthreads();
    }
    if (threadIdx.x == 0) g_rowptr[r][NN] = carry;
}

__global__ void k_fill(const void* __restrict__ edge) {
    int is64 = g_is64;
    int gid = blockIdx.x * blockDim.x + threadIdx.x;
    if (gid >= NREL * EE) return;
    int r = gid / EE, e = gid - r * EE;
    int src = idx_at(edge, ((long long)r * 2 + 0) * EE + e, is64);
    int dst = idx_at(edge, ((long long)r * 2 + 1) * EE + e, is64);
    int slot = atomicAdd(&g_cursor[r][dst], 1);
    g_col[r][slot] = src;
}

// ---------------- input convert ----------------
__global__ void k_split(const float* __restrict__ x, __nv_bfloat16* __restrict__ b, int n) {
    int i = blockIdx.x * blockDim.x + threadIdx.x;
    if (i >= n) return;
    b[i] = __float2bfloat16(x[i]);
}

// ---------------- weight prep: transpose + bf16, merged self+neighbor B ----------------
__global__ void k_wprep(const float* __restrict__ We, const float* __restrict__ Wl,
                        const float* __restrict__ Wr, const float* __restrict__ bl) {
    int gid = blockIdx.x * blockDim.x + threadIdx.x;
    const int grp[2][3] = {{0, 1, 3}, {2, 4, 5}};
    if (gid < 2 * HH * DIN) {               // emb weights -> [t][n][k]
        int t = gid >> 15, rem = gid & 32767, n = rem >> 7, k = rem & 127;
        g_web[t * HH * DIN + n * DIN + k] =
            __float2bfloat16(We[((long long)t * DIN + k) * HH + n]);
    }
    if (gid < LL * 2 * 1024 * HH) {         // merged B: rows 0-255 self-sum, 256.. neighbor rels
        int lt = gid >> 18, rem = gid & 0x3FFFF, row = rem >> 8, k = rem & 255;
        int layer = lt >> 1, t = lt & 1;
        float v;
        if (row < 256) {
            int n = row;
            const float* W = Wr + (long long)layer * NREL * HH * HH;
            v = W[(long long)grp[t][0] * HH * HH + k * HH + n] +
                W[(long long)grp[t][1] * HH * HH + k * HH + n] +
                W[(long long)grp[t][2] * HH * HH + k * HH + n];
        } else {
            int q = (row - 256) >> 8, n = row & 255;
            int rel = t * 3 + q;
            v = Wl[(((long long)layer * NREL + rel) * HH + k) * HH + n];
        }
        g_wcat[(long long)lt * 1024 * HH + row * HH + k] = __float2bfloat16(v);
    }
    if (gid < LL * 2 * HH) {
        int lt = gid >> 8, c = gid & 255;
        int layer = lt >> 1, t = lt & 1;
        const float* b = bl + (long long)layer * NREL * HH;
        g_blsum[lt * HH + c] = b[grp[t][0] * HH + c] + b[grp[t][1] * HH + c] +
                               b[grp[t][2] * HH + c];
    }
}

// ---------------- HMMA GEMM (bf16x1, cp.async double-buffered) ----------------
// A: bf16 [M][K] row-major. B: bf16 [gridDim.y*128][K] K-major rows.
// CTA tile 128x128, BK=32, 8 warps (4M x 2N), warp tile 32x64.
// by < selfN: C = Cf (fp32, +bias); dualOut also writes Cbf (bf16).
// by >= selfN: C = Cbf + ((by>>1)-1)*cbStride (bf16), output col = (by&1)*128 + ...
#define SPAD 40
#define BUFB (128 * SPAD * 2)   // 10240 bytes per buffer per array

__global__ void __launch_bounds__(256, 2) k_gemm(
    const __nv_bfloat16* __restrict__ A, const __nv_bfloat16* __restrict__ B,
    float* __restrict__ Cf, const float* __restrict__ bias,
    __nv_bfloat16* __restrict__ Cbf, long long cbStride,
    int selfN, int dualOut, int M, int K)
{
    __shared__ __nv_bfloat16 sA[2 * 128 * SPAD];
    __shared__ __nv_bfloat16 sB[2 * 128 * SPAD];
    int tid = threadIdx.x, wid = tid >> 5, lane = tid & 31;
    long long bm = (long long)blockIdx.x * 128;
    int nb = blockIdx.y * 128;      // B row block
    int wm = (wid & 3) * 32;
    int wn = (wid >> 2) * 64;
    uint32_t sbA = smem_u32(sA), sbB = smem_u32(sB);

    float acc[2][8][4];
#pragma unroll
    for (int i = 0; i < 2; i++)
#pragma unroll
        for (int j = 0; j < 8; j++)
#pragma unroll
            for (int q = 0; q < 4; q++) acc[i][j][q] = 0.0f;

    int a_row = (lane & 7) + ((lane >> 3) & 1) * 8;
    int a_col = (lane >> 4) * 8;
    int b_row = lane & 7;
    int b_col = (lane >> 3) * 8;
    int nch = K >> 5;

#define ISSUE_STAGE(c, buf) do {                                                   \
        _Pragma("unroll")                                                          \
        for (int i = tid; i < 512; i += 256) {                                     \
            int row = i >> 2, seg = (i & 3) << 3;                                  \
            uint32_t so = (buf) * BUFB + (uint32_t)(row * SPAD + seg) * 2;         \
            int av = (bm + row < M) ? 16 : 0;                                      \
            const __nv_bfloat16* ga = A + ((bm + row < M) ?                        \
                                           ((bm + row) * K + (c) * 32 + seg) : 0); \
            const __nv_bfloat16* gb = B + ((long long)(nb + row) * K + (c) * 32 + seg); \
            cp16(sbA + so, ga, av);                                                \
            cp16(sbB + so, gb, 16);                                                \
        }                                                                          \
        asm volatile("cp.async.commit_group;");                                    \
    } while (0)

    ISSUE_STAGE(0, 0);
    for (int c = 0; c < nch; c++) {
        if (c + 1 < nch) {
            ISSUE_STAGE(c + 1, (c + 1) & 1);
            asm volatile("cp.async.wait_group 1;");
        } else {
            asm volatile("cp.async.wait_group 0;");
        }
        __syncthreads();

        uint32_t bA = sbA + (c & 1) * BUFB, bB = sbB + (c & 1) * BUFB;
        uint32_t bf[8][4];
#pragma unroll
        for (int nt = 0; nt < 8; nt++)
            ldm_x4(bf[nt], bB + (uint32_t)((wn + nt * 8 + b_row) * SPAD + b_col) * 2);
#pragma unroll
        for (int ks = 0; ks < 2; ks++) {
            uint32_t af[2][4];
#pragma unroll
            for (int mt = 0; mt < 2; mt++)
                ldm_x4(af[mt], bA + (uint32_t)((wm + mt * 16 + a_row) * SPAD + ks * 16 + a_col) * 2);
#pragma unroll
            for (int mt = 0; mt < 2; mt++)
#pragma unroll
                for (int nt = 0; nt < 8; nt++)
                    mma_bf16(acc[mt][nt], af[mt], &bf[nt][ks * 2]);
        }
        __syncthreads();
    }
#undef ISSUE_STAGE

    // ---- epilogue ----
    bool isSelf = (int)blockIdx.y < selfN;
    __nv_bfloat16* Cb = nullptr;
    if (Cbf) Cb = isSelf ? Cbf : (Cbf + (long long)((blockIdx.y >> 1) - 1) * cbStride);
    int gidr = lane >> 2, tig = lane & 3;
#pragma unroll
    for (int mt = 0; mt < 2; mt++) {
        long long r0 = bm + wm + mt * 16 + gidr;
        long long r1 = r0 + 8;
#pragma unroll
        for (int nt = 0; nt < 8; nt++) {
            int col = (blockIdx.y & 1) * 128 + wn + nt * 8 + tig * 2;
            float b0 = 0.f, b1 = 0.f;
            if (isSelf && bias) { b0 = bias[col]; b1 = bias[col + 1]; }
            if (r0 < M) {
                float v0 = acc[mt][nt][0] + b0, v1 = acc[mt][nt][1] + b1;
                if (isSelf) {
                    *(float2*)&Cf[r0 * 256 + col] = make_float2(v0, v1);
                    if (dualOut) *(__nv_bfloat162*)&Cb[r0 * 256 + col] = __floats2bfloat162_rn(v0, v1);
                } else {
                    *(__nv_bfloat162*)&Cb[r0 * 256 + col] = __floats2bfloat162_rn(v0, v1);
                }
            }
            if (r1 < M) {
                float v2 = acc[mt][nt][2] + b0, v3 = acc[mt][nt][3] + b1;
                if (isSelf) {
                    *(float2*)&Cf[r1 * 256 + col] = make_float2(v2, v3);
                    if (dualOut) *(__nv_bfloat162*)&Cb[r1 * 256 + col] = __floats2bfloat162_rn(v2, v3);
                } else {
                    *(__nv_bfloat162*)&Cb[r1 * 256 + col] = __floats2bfloat162_rn(v2, v3);
                }
            }
        }
    }
}

// ---------------- gather-mean aggregation (bf16 source, fp32 accumulate) ----------------
__global__ void k_agg(int r0, int r1, int r2, float* __restrict__ acc) {
    int w = (blockIdx.x * blockDim.x + threadIdx.x) >> 5;
    int lane = threadIdx.x & 31;
    if (w >= NN) return;
    float t[8] = {0.f, 0.f, 0.f, 0.f, 0.f, 0.f, 0.f, 0.f};
    int rel[3] = {r0, r1, r2};
#pragma unroll
    for (int q = 0; q < 3; q++) {
        int r = rel[q];
        int b = g_rowptr[r][w], e = g_rowptr[r][w + 1];
        float s[8] = {0.f, 0.f, 0.f, 0.f, 0.f, 0.f, 0.f, 0.f};
        const uint4* base = (const uint4*)(g_tmpb + (long long)r * NN * HH);
        int j = b;
        for (; j + 1 < e; j += 2) {
            uint4 va = base[(long long)g_col[r][j] * 32 + lane];
            uint4 vb = base[(long long)g_col[r][j + 1] * 32 + lane];
            const __nv_bfloat162* ha = (const __nv_bfloat162*)&va;
            const __nv_bfloat162* hb = (const __nv_bfloat162*)&vb;
#pragma unroll
            for (int u = 0; u < 4; u++) {
                float2 fa = __bfloat1622float2(ha[u]);
                float2 fb = __bfloat1622float2(hb[u]);
                s[2 * u] += fa.x + fb.x;
                s[2 * u + 1] += fa.y + fb.y;
            }
        }
        if (j < e) {
            uint4 va = base[(long long)g_col[r][j] * 32 + lane];
            const __nv_bfloat162* ha = (const __nv_bfloat162*)&va;
#pragma unroll
            for (int u = 0; u < 4; u++) {
                float2 fa = __bfloat1622float2(ha[u]);
                s[2 * u] += fa.x;
                s[2 * u + 1] += fa.y;
            }
        }
        float inv = (e > b) ? 1.0f / (float)(e - b) : 0.0f;
#pragma unroll
        for (int u = 0; u < 8; u++) t[u] = fmaf(s[u], inv, t[u]);
    }
    float4* arow = (float4*)(acc + (long long)w * HH + lane * 8);
    float4 o0 = arow[0], o1 = arow[1];
    arow[0] = make_float4(o0.x + t[0], o0.y + t[1], o0.z + t[2], o0.w + t[3]);
    arow[1] = make_float4(o1.x + t[4], o1.y + t[5], o1.z + t[6], o1.w + t[7]);
}

// ---------------- batchnorm ----------------
__global__ void k_bnstats(const float* __restrict__ acc, float* __restrict__ st) {
    int c = threadIdx.x;
    float s = 0.f, q = 0.f;
    for (int r = blockIdx.x; r < NN; r += gridDim.x) {
        float v = acc[(long long)r * HH + c];
        s += v;
        q += v * v;
    }
    atomicAdd(&st[c], s);
    atomicAdd(&st[HH + c], q);
}

__global__ void k_bnapply(const float* __restrict__ acc, float* __restrict__ x,
                          __nv_bfloat16* __restrict__ xb,
                          const float* __restrict__ st, const float* __restrict__ gamma,
                          const float* __restrict__ beta, int resid) {
    int c = threadIdx.x;
    float meanA = st[c] * (1.0f / NN);
    float varA  = st[HH + c] * (1.0f / NN) - meanA * meanA;
    float varX  = varA * (1.0f / 9.0f);
    float rs    = rsqrtf(varX + 1e-5f);
    float scale = gamma[c] * rs * (1.0f / 3.0f);
    float shift = beta[c] - meanA * scale;
    for (int r = blockIdx.x; r < NN; r += gridDim.x) {
        long long i = (long long)r * HH + c;
        float y = fmaxf(fmaf(acc[i], scale, shift), 0.0f);
        float xn = resid ? (x[i] + y) : y;
        x[i] = xn;
        xb[i] = __float2bfloat16(xn);
    }
}

// ---------------- pooling + head ----------------
__global__ void k_pcnt(const void* __restrict__ bv, const void* __restrict__ bp) {
    int is64 = g_is64;
    int gid = blockIdx.x * blockDim.x + threadIdx.x;
    if (gid >= 2 * NN) return;
    int t = gid / NN, i = gid - t * NN;
    int g = t ? idx_at(bp, i, is64) : idx_at(bv, i, is64);
    atomicAdd(&g_pcnt[t][g], 1);
}

__global__ void k_pool(const float* __restrict__ x, const void* __restrict__ batch,
                       float* __restrict__ pool) {
    int is64 = g_is64;
    int c = threadIdx.x;
    int r0 = blockIdx.x * 64;
    int r1 = min(r0 + 64, NN);
    float local = 0.f;
    int gprev = -1;
    for (int r = r0; r < r1; r++) {
        int g = idx_at(batch, r, is64);
        if (g != gprev) {
            if (gprev >= 0) atomicAdd(&pool[gprev * HH + c], local);
            local = 0.f;
            gprev = g;
        }
        local += x[(long long)r * HH + c];
    }
    if (gprev >= 0) atomicAdd(&pool[gprev * HH + c], local);
}

__global__ void k_final(const float* __restrict__ Wo, const float* __restrict__ bo,
                        float* __restrict__ out) {
    int g = threadIdx.x >> 5, lane = threadIdx.x & 31;
    if (g >= GG) return;
    float cv = (float)max(g_pcnt[0][g], 1);
    float cp = (float)max(g_pcnt[1][g], 1);
    float s = 0.f;
    for (int c = lane; c < HH; c += 32)
        s += g_pool[0][g * HH + c] / cv * Wo[c] + g_pool[1][g * HH + c] / cp * Wo[HH + c];
#pragma unroll
    for (int off = 16; off; off >>= 1) s += __shfl_down_sync(0xffffffffu, s, off);
    if (lane == 0) out[g] = 1.0f / (1.0f + expf(-(s + bo[0])));
}

// ---------------- launcher ----------------
extern "C" void kernel_launch(void* const* d_in, const int* in_sizes, int n_in,
                              void* d_out, int out_size) {
    const float* x_vuln  = (const float*)d_in[0];
    const float* x_patch = (const float*)d_in[1];
    const float* W_emb   = (const float*)d_in[2];
    const float* b_emb   = (const float*)d_in[3];
    const float* W_l     = (const float*)d_in[4];
    const float* b_l     = (const float*)d_in[5];
    const float* W_r     = (const float*)d_in[6];
    const float* gamma   = (const float*)d_in[7];
    const float* beta    = (const float*)d_in[8];
    const float* W_out   = (const float*)d_in[9];
    const float* b_out   = (const float*)d_in[10];
    const void* edge     = d_in[11];
    const void* batch_v  = d_in[12];
    const void* batch_p  = d_in[13];
    float* out = (float*)d_out;

    void* p;
    cudaGetSymbolAddress(&p, g_x);     float* x0 = (float*)p;  float* x1 = x0 + (size_t)NN * HH;
    cudaGetSymbolAddress(&p, g_accb);  float* a0 = (float*)p;  float* a1 = a0 + (size_t)NN * HH;
    cudaGetSymbolAddress(&p, g_tmpb);  __nv_bfloat16* tmpb = (__nv_bfloat16*)p;
    cudaGetSymbolAddress(&p, g_xb);    __nv_bfloat16* xb = (__nv_bfloat16*)p;
    cudaGetSymbolAddress(&p, g_inb);   __nv_bfloat16* inb = (__nv_bfloat16*)p;
    cudaGetSymbolAddress(&p, g_web);   __nv_bfloat16* web = (__nv_bfloat16*)p;
    cudaGetSymbolAddress(&p, g_wcat);  __nv_bfloat16* wcat = (__nv_bfloat16*)p;
    cudaGetSymbolAddress(&p, g_blsum); float* bls = (float*)p;
    cudaGetSymbolAddress(&p, g_deg);   void* degp = p;
    cudaGetSymbolAddress(&p, g_stats); float* stats = (float*)p;
    cudaGetSymbolAddress(&p, g_pool);  float* pool = (float*)p;
    cudaGetSymbolAddress(&p, g_pcnt);  void* pcnt = p;

    // index dtype detection + CSR build
    k_detect<<<1, 256>>>((const unsigned int*)edge);
    cudaMemsetAsync(degp, 0, sizeof(int) * NREL * NN, 0);
    k_hist<<<(NREL * EE + 255) / 256, 256>>>(edge);
    k_scan<<<NREL, 1024>>>();
    k_fill<<<(NREL * EE + 255) / 256, 256>>>(edge);

    // weight prep + input convert
    k_wprep<<<4096, 256>>>(W_emb, W_l, W_r, b_l);
    k_split<<<(NN * DIN + 255) / 256, 256>>>(x_vuln,  inb,            NN * DIN);
    k_split<<<(NN * DIN + 255) / 256, 256>>>(x_patch, inb + NN * DIN, NN * DIN);

    const int MB = (NN + 127) / 128;
    size_t xs = (size_t)NN * HH;
    // embedding GEMMs (K=128): fp32 out + bf16 dual out
    k_gemm<<<dim3(MB, 2, 1), 256>>>(inb, web, x0, b_emb, xb,
                                    0, 2, 1, NN, DIN);
    k_gemm<<<dim3(MB, 2, 1), 256>>>(inb + NN * DIN, web + HH * DIN, x1, b_emb + HH, xb + xs,
                                    0, 2, 1, NN, DIN);

    for (int layer = 0; layer < LL; layer++) {
        // merged self(fp32->acc,+bias) + 3 neighbor (bf16->tmpb) GEMM per source type
        k_gemm<<<dim3(MB, 8, 1), 256>>>(xb, wcat + (size_t)(layer * 2 + 0) * 1024 * HH,
                                        a0, bls + (layer * 2 + 0) * HH,
                                        tmpb, (long long)NN * HH, 2, 0, NN, HH);
        k_gemm<<<dim3(MB, 8, 1), 256>>>(xb + xs, wcat + (size_t)(layer * 2 + 1) * 1024 * HH,
                                        a1, bls + (layer * 2 + 1) * HH,
                                        tmpb + 3 * xs, (long long)NN * HH, 2, 0, NN, HH);
        // gather-mean
        int aggBlocks = (NN * 32 + 255) / 256;
        k_agg<<<aggBlocks, 256>>>(0, 1, 3, a0);
        k_agg<<<aggBlocks, 256>>>(2, 4, 5, a1);
        // batchnorm + relu (+ residual)
        cudaMemsetAsync(stats, 0, sizeof(float) * 2 * 2 * HH, 0);
        k_bnstats<<<128, 256>>>(a0, stats);
        k_bnstats<<<128, 256>>>(a1, stats + 2 * HH);
        k_bnapply<<<256, 256>>>(a0, x0, xb, stats,
                                gamma + (layer * 2 + 0) * HH, beta + (layer * 2 + 0) * HH, layer > 0);
        k_bnapply<<<256, 256>>>(a1, x1, xb + xs, stats + 2 * HH,
                                gamma + (layer * 2 + 1) * HH, beta + (layer * 2 + 1) * HH, layer > 0);
    }

    // pooling + head
    cudaMemsetAsync(pool, 0, sizeof(float) * 2 * GG * HH, 0);
    cudaMemsetAsync(pcnt, 0, sizeof(int) * 2 * GG, 0);
    k_pcnt<<<(2 * NN + 255) / 256, 256>>>(batch_v, batch_p);
    k_pool<<<(NN + 63) / 64, 256>>>(x0, batch_v, pool);
    k_pool<<<(NN + 63) / 64, 256>>>(x1, batch_p, pool + GG * HH);
    k_final<<<1, 1024>>>(W_out, b_out, out);
}

// round 9
// speedup vs baseline: 2.6310x; 1.2108x over previous
#include <cuda_runtime.h>
#include <cuda_bf16.h>
#include <math.h>
#include <stdint.h>

#define NN   20000
#define EE   320000
#define DIN  128
#define HH   256
#define LL   2
#define GG   32
#define NREL 6

// ---------------- device scratch ----------------
__device__ float g_x[2 * NN * HH];
__device__ float g_accb[2 * NN * HH];
__device__ __nv_bfloat16 g_tmpb[NREL * NN * HH];     // neighbor GEMM outputs (bf16)
__device__ __nv_bfloat16 g_xb[2 * NN * HH];          // bf16 copy of x (GEMM A input)
__device__ __nv_bfloat16 g_inb[2 * NN * DIN];        // bf16 copy of raw inputs
__device__ __nv_bfloat16 g_web[2 * HH * DIN];        // emb weights [t][n][k]
__device__ __nv_bfloat16 g_wcat[LL * 2 * 1024 * HH]; // merged [l][t][1024 rows][k]
__device__ float g_blsum[LL * 2 * HH];
__device__ int   g_deg[NREL][NN];
__device__ int   g_rowptr[NREL][NN + 1];
__device__ int   g_cursor[NREL][NN];
__device__ int   g_col[NREL][EE];
__device__ float g_stats[2][2 * HH];
__device__ float g_pool[2][GG * HH];
__device__ int   g_pcnt[2][GG];
__device__ int   g_is64;

// ---------------- helpers ----------------
__device__ __forceinline__ int idx_at(const void* p, long long i, int is64) {
    return is64 ? (int)((const long long*)p)[i] : ((const int*)p)[i];
}
__device__ __forceinline__ uint32_t smem_u32(const void* p) {
    uint32_t a;
    asm("{ .reg .u64 t; cvta.to.shared.u64 t, %1; cvt.u32.u64 %0, t; }" : "=r"(a) : "l"(p));
    return a;
}
__device__ __forceinline__ void ldm_x4(uint32_t* r, uint32_t addr) {
    asm volatile("ldmatrix.sync.aligned.m8n8.x4.shared.b16 {%0,%1,%2,%3}, [%4];"
                 : "=r"(r[0]), "=r"(r[1]), "=r"(r[2]), "=r"(r[3]) : "r"(addr));
}
__device__ __forceinline__ void mma_bf16(float* c, const uint32_t* a, const uint32_t* b) {
    asm volatile("mma.sync.aligned.m16n8k16.row.col.f32.bf16.bf16.f32 "
                 "{%0,%1,%2,%3}, {%4,%5,%6,%7}, {%8,%9}, {%0,%1,%2,%3};"
                 : "+f"(c[0]), "+f"(c[1]), "+f"(c[2]), "+f"(c[3])
                 : "r"(a[0]), "r"(a[1]), "r"(a[2]), "r"(a[3]), "r"(b[0]), "r"(b[1]));
}
__device__ __forceinline__ void cp16(uint32_t dst, const void* src, int nbytes) {
    asm volatile("cp.async.cg.shared.global [%0], [%1], 16, %2;"
                 :: "r"(dst), "l"(src), "r"(nbytes));
}
__device__ __forceinline__ void addv(float* s, uint4 v) {
    const __nv_bfloat162* h = (const __nv_bfloat162*)&v;
#pragma unroll
    for (int u = 0; u < 4; u++) {
        float2 f = __bfloat1622float2(h[u]);
        s[2 * u] += f.x;
        s[2 * u + 1] += f.y;
    }
}

// ---------------- index dtype detection ----------------
__global__ void k_detect(const unsigned int* __restrict__ e) {
    __shared__ int any;
    if (threadIdx.x == 0) any = 0;
    __syncthreads();
    unsigned int v = 0;
    for (int i = threadIdx.x; i < 2048; i += blockDim.x)
        v |= e[(long long)i * 1874 + 1];
    if (v) any = 1;
    __syncthreads();
    if (threadIdx.x == 0) g_is64 = any ? 0 : 1;
}

// ---------------- CSR construction ----------------
__global__ void k_hist(const void* __restrict__ edge) {
    int is64 = g_is64;
    int gid = blockIdx.x * blockDim.x + threadIdx.x;
    if (gid >= NREL * EE) return;
    int r = gid / EE, e = gid - r * EE;
    int dst = idx_at(edge, ((long long)r * 2 + 1) * EE + e, is64);
    atomicAdd(&g_deg[r][dst], 1);
}

// single-pass block scan: 6 blocks x 1024 threads, 20 elems/thread in registers
__global__ void __launch_bounds__(1024) k_scan() {
    int r = blockIdx.x;
    const int PER = 20;
    int tid = threadIdx.x;
    int lane = tid & 31, wid = tid >> 5;
    int start = tid * PER;
    int loc[PER];
    int sum = 0;
#pragma unroll
    for (int i = 0; i < PER; i++) {
        int idx = start + i;
        int v = (idx < NN) ? g_deg[r][idx] : 0;
        loc[i] = sum;
        sum += v;
    }
    // block exclusive scan of per-thread sums
    __shared__ int wsum[32];
    int incl = sum;
#pragma unroll
    for (int o = 1; o < 32; o <<= 1) {
        int x = __shfl_up_sync(0xffffffffu, incl, o);
        if (lane >= o) incl += x;
    }
    if (lane == 31) wsum[wid] = incl;
    __syncthreads();
    if (wid == 0) {
        int v = wsum[lane];
#pragma unroll
        for (int o = 1; o < 32; o <<= 1) {
            int x = __shfl_up_sync(0xffffffffu, v, o);
            if (lane >= o) v += x;
        }
        wsum[lane] = v;
    }
    __syncthreads();
    int prefix = incl - sum + (wid ? wsum[wid - 1] : 0);
#pragma unroll
    for (int i = 0; i < PER; i++) {
        int idx = start + i;
        if (idx < NN) {
            int ex = prefix + loc[i];
            g_rowptr[r][idx] = ex;
            g_cursor[r][idx] = ex;
        }
    }
    if (tid == 1023) g_rowptr[r][NN] = prefix + sum;
}

__global__ void k_fill(const void* __restrict__ edge) {
    int is64 = g_is64;
    int gid = blockIdx.x * blockDim.x + threadIdx.x;
    if (gid >= NREL * EE) return;
    int r = gid / EE, e = gid - r * EE;
    int src = idx_at(edge, ((long long)r * 2 + 0) * EE + e, is64);
    int dst = idx_at(edge, ((long long)r * 2 + 1) * EE + e, is64);
    int slot = atomicAdd(&g_cursor[r][dst], 1);
    g_col[r][slot] = src;
}

// ---------------- input convert ----------------
__global__ void k_split(const float* __restrict__ x, __nv_bfloat16* __restrict__ b, int n) {
    int i = blockIdx.x * blockDim.x + threadIdx.x;
    if (i >= n) return;
    b[i] = __float2bfloat16(x[i]);
}

// ---------------- weight prep ----------------
__global__ void k_wprep(const float* __restrict__ We, const float* __restrict__ Wl,
                        const float* __restrict__ Wr, const float* __restrict__ bl) {
    int gid = blockIdx.x * blockDim.x + threadIdx.x;
    const int grp[2][3] = {{0, 1, 3}, {2, 4, 5}};
    if (gid < 2 * HH * DIN) {
        int t = gid >> 15, rem = gid & 32767, n = rem >> 7, k = rem & 127;
        g_web[t * HH * DIN + n * DIN + k] =
            __float2bfloat16(We[((long long)t * DIN + k) * HH + n]);
    }
    if (gid < LL * 2 * 1024 * HH) {
        int lt = gid >> 18, rem = gid & 0x3FFFF, row = rem >> 8, k = rem & 255;
        int layer = lt >> 1, t = lt & 1;
        float v;
        if (row < 256) {
            int n = row;
            const float* W = Wr + (long long)layer * NREL * HH * HH;
            v = W[(long long)grp[t][0] * HH * HH + k * HH + n] +
                W[(long long)grp[t][1] * HH * HH + k * HH + n] +
                W[(long long)grp[t][2] * HH * HH + k * HH + n];
        } else {
            int q = (row - 256) >> 8, n = row & 255;
            int rel = t * 3 + q;
            v = Wl[(((long long)layer * NREL + rel) * HH + k) * HH + n];
        }
        g_wcat[(long long)lt * 1024 * HH + row * HH + k] = __float2bfloat16(v);
    }
    if (gid < LL * 2 * HH) {
        int lt = gid >> 8, c = gid & 255;
        int layer = lt >> 1, t = lt & 1;
        const float* b = bl + (long long)layer * NREL * HH;
        g_blsum[lt * HH + c] = b[grp[t][0] * HH + c] + b[grp[t][1] * HH + c] +
                               b[grp[t][2] * HH + c];
    }
}

// ---------------- HMMA GEMM (bf16x1, cp.async double-buffered, z-batched types) ----------------
#define SPAD 40
#define BUFB (128 * SPAD * 2)

__global__ void __launch_bounds__(256, 2) k_gemm(
    const __nv_bfloat16* __restrict__ A0, long long aStr,
    const __nv_bfloat16* __restrict__ B0, long long bStr,
    float* __restrict__ Cf0, long long cfStr,
    const float* __restrict__ bias0, int biasStr,
    __nv_bfloat16* __restrict__ Cb0, long long cbzStr, long long cbStride,
    int selfN, int dualOut, int M, int K)
{
    __shared__ __nv_bfloat16 sA[2 * 128 * SPAD];
    __shared__ __nv_bfloat16 sB[2 * 128 * SPAD];
    int z = blockIdx.z;
    const __nv_bfloat16* A = A0 + (long long)z * aStr;
    const __nv_bfloat16* B = B0 + (long long)z * bStr;
    float* Cf = Cf0 ? Cf0 + (long long)z * cfStr : nullptr;
    const float* bias = bias0 ? bias0 + (long long)z * biasStr : nullptr;
    __nv_bfloat16* Cbz = Cb0 ? Cb0 + (long long)z * cbzStr : nullptr;

    int tid = threadIdx.x, wid = tid >> 5, lane = tid & 31;
    long long bm = (long long)blockIdx.x * 128;
    int nb = blockIdx.y * 128;
    int wm = (wid & 3) * 32;
    int wn = (wid >> 2) * 64;
    uint32_t sbA = smem_u32(sA), sbB = smem_u32(sB);

    float acc[2][8][4];
#pragma unroll
    for (int i = 0; i < 2; i++)
#pragma unroll
        for (int j = 0; j < 8; j++)
#pragma unroll
            for (int q = 0; q < 4; q++) acc[i][j][q] = 0.0f;

    int a_row = (lane & 7) + ((lane >> 3) & 1) * 8;
    int a_col = (lane >> 4) * 8;
    int b_row = lane & 7;
    int b_col = (lane >> 3) * 8;
    int nch = K >> 5;

#define ISSUE_STAGE(c, buf) do {                                                   \
        _Pragma("unroll")                                                          \
        for (int i = tid; i < 512; i += 256) {                                     \
            int row = i >> 2, seg = (i & 3) << 3;                                  \
            uint32_t so = (buf) * BUFB + (uint32_t)(row * SPAD + seg) * 2;         \
            int av = (bm + row < M) ? 16 : 0;                                      \
            const __nv_bfloat16* ga = A + ((bm + row < M) ?                        \
                                           ((bm + row) * K + (c) * 32 + seg) : 0); \
            const __nv_bfloat16* gb = B + ((long long)(nb + row) * K + (c) * 32 + seg); \
            cp16(sbA + so, ga, av);                                                \
            cp16(sbB + so, gb, 16);                                                \
        }                                                                          \
        asm volatile("cp.async.commit_group;");                                    \
    } while (0)

    ISSUE_STAGE(0, 0);
    for (int c = 0; c < nch; c++) {
        if (c + 1 < nch) {
            ISSUE_STAGE(c + 1, (c + 1) & 1);
            asm volatile("cp.async.wait_group 1;");
        } else {
            asm volatile("cp.async.wait_group 0;");
        }
        __syncthreads();

        uint32_t bA = sbA + (c & 1) * BUFB, bB = sbB + (c & 1) * BUFB;
        uint32_t bf[8][4];
#pragma unroll
        for (int nt = 0; nt < 8; nt++)
            ldm_x4(bf[nt], bB + (uint32_t)((wn + nt * 8 + b_row) * SPAD + b_col) * 2);
#pragma unroll
        for (int ks = 0; ks < 2; ks++) {
            uint32_t af[2][4];
#pragma unroll
            for (int mt = 0; mt < 2; mt++)
                ldm_x4(af[mt], bA + (uint32_t)((wm + mt * 16 + a_row) * SPAD + ks * 16 + a_col) * 2);
#pragma unroll
            for (int mt = 0; mt < 2; mt++)
#pragma unroll
                for (int nt = 0; nt < 8; nt++)
                    mma_bf16(acc[mt][nt], af[mt], &bf[nt][ks * 2]);
        }
        __syncthreads();
    }
#undef ISSUE_STAGE

    // ---- epilogue ----
    bool isSelf = (int)blockIdx.y < selfN;
    __nv_bfloat16* Cb = nullptr;
    if (Cbz) Cb = isSelf ? Cbz : (Cbz + (long long)((blockIdx.y >> 1) - 1) * cbStride);
    int gidr = lane >> 2, tig = lane & 3;
#pragma unroll
    for (int mt = 0; mt < 2; mt++) {
        long long r0 = bm + wm + mt * 16 + gidr;
        long long r1 = r0 + 8;
#pragma unroll
        for (int nt = 0; nt < 8; nt++) {
            int col = (blockIdx.y & 1) * 128 + wn + nt * 8 + tig * 2;
            float b0 = 0.f, b1 = 0.f;
            if (isSelf && bias) { b0 = bias[col]; b1 = bias[col + 1]; }
            if (r0 < M) {
                float v0 = acc[mt][nt][0] + b0, v1 = acc[mt][nt][1] + b1;
                if (isSelf) {
                    *(float2*)&Cf[r0 * 256 + col] = make_float2(v0, v1);
                    if (dualOut) *(__nv_bfloat162*)&Cb[r0 * 256 + col] = __floats2bfloat162_rn(v0, v1);
                } else {
                    *(__nv_bfloat162*)&Cb[r0 * 256 + col] = __floats2bfloat162_rn(v0, v1);
                }
            }
            if (r1 < M) {
                float v2 = acc[mt][nt][2] + b0, v3 = acc[mt][nt][3] + b1;
                if (isSelf) {
                    *(float2*)&Cf[r1 * 256 + col] = make_float2(v2, v3);
                    if (dualOut) *(__nv_bfloat162*)&Cb[r1 * 256 + col] = __floats2bfloat162_rn(v2, v3);
                } else {
                    *(__nv_bfloat162*)&Cb[r1 * 256 + col] = __floats2bfloat162_rn(v2, v3);
                }
            }
        }
    }
}

// ---------------- gather-mean aggregation (shfl col broadcast + 4-deep MLP) ----------------
__global__ void k_agg(int r0, int r1, int r2, float* __restrict__ acc) {
    int w = (blockIdx.x * blockDim.x + threadIdx.x) >> 5;
    int lane = threadIdx.x & 31;
    if (w >= NN) return;
    float t[8] = {0.f, 0.f, 0.f, 0.f, 0.f, 0.f, 0.f, 0.f};
    int rel[3] = {r0, r1, r2};
#pragma unroll
    for (int q = 0; q < 3; q++) {
        int r = rel[q];
        int b = g_rowptr[r][w], e = g_rowptr[r][w + 1];
        float s[8] = {0.f, 0.f, 0.f, 0.f, 0.f, 0.f, 0.f, 0.f};
        const uint4* base = (const uint4*)(g_tmpb + (long long)r * NN * HH);
        for (int j0 = b; j0 < e; j0 += 32) {
            int n = min(32, e - j0);
            int myc = (lane < n) ? g_col[r][j0 + lane] : 0;
            int k = 0;
            for (; k + 3 < n; k += 4) {
                int c0 = __shfl_sync(0xffffffffu, myc, k);
                int c1 = __shfl_sync(0xffffffffu, myc, k + 1);
                int c2 = __shfl_sync(0xffffffffu, myc, k + 2);
                int c3 = __shfl_sync(0xffffffffu, myc, k + 3);
                uint4 v0 = base[(long long)c0 * 32 + lane];
                uint4 v1 = base[(long long)c1 * 32 + lane];
                uint4 v2 = base[(long long)c2 * 32 + lane];
                uint4 v3 = base[(long long)c3 * 32 + lane];
                addv(s, v0); addv(s, v1); addv(s, v2); addv(s, v3);
            }
            for (; k < n; k++) {
                int c0 = __shfl_sync(0xffffffffu, myc, k);
                uint4 v0 = base[(long long)c0 * 32 + lane];
                addv(s, v0);
            }
        }
        float inv = (e > b) ? 1.0f / (float)(e - b) : 0.0f;
#pragma unroll
        for (int u = 0; u < 8; u++) t[u] = fmaf(s[u], inv, t[u]);
    }
    float4* arow = (float4*)(acc + (long long)w * HH + lane * 8);
    float4 o0 = arow[0], o1 = arow[1];
    arow[0] = make_float4(o0.x + t[0], o0.y + t[1], o0.z + t[2], o0.w + t[3]);
    arow[1] = make_float4(o1.x + t[4], o1.y + t[5], o1.z + t[6], o1.w + t[7]);
}

// ---------------- batchnorm (y-batched types) ----------------
__global__ void k_bnstats(const float* __restrict__ acc0, float* __restrict__ st0) {
    int t = blockIdx.y;
    const float* acc = acc0 + (long long)t * NN * HH;
    float* st = st0 + t * 2 * HH;
    int c = threadIdx.x;
    float s = 0.f, q = 0.f;
    for (int r = blockIdx.x; r < NN; r += gridDim.x) {
        float v = acc[(long long)r * HH + c];
        s += v;
        q += v * v;
    }
    atomicAdd(&st[c], s);
    atomicAdd(&st[HH + c], q);
}

__global__ void k_bnapply(const float* __restrict__ acc0, float* __restrict__ x0,
                          __nv_bfloat16* __restrict__ xb0,
                          const float* __restrict__ st0, const float* __restrict__ gamma0,
                          const float* __restrict__ beta0, int resid) {
    int t = blockIdx.y;
    long long off = (long long)t * NN * HH;
    const float* acc = acc0 + off;
    float* x = x0 + off;
    __nv_bfloat16* xb = xb0 + off;
    const float* st = st0 + t * 2 * HH;
    const float* gamma = gamma0 + t * HH;
    const float* beta  = beta0 + t * HH;
    int c = threadIdx.x;
    float meanA = st[c] * (1.0f / NN);
    float varA  = st[HH + c] * (1.0f / NN) - meanA * meanA;
    float varX  = varA * (1.0f / 9.0f);
    float rs    = rsqrtf(varX + 1e-5f);
    float scale = gamma[c] * rs * (1.0f / 3.0f);
    float shift = beta[c] - meanA * scale;
    for (int r = blockIdx.x; r < NN; r += gridDim.x) {
        long long i = (long long)r * HH + c;
        float y = fmaxf(fmaf(acc[i], scale, shift), 0.0f);
        float xn = resid ? (x[i] + y) : y;
        x[i] = xn;
        xb[i] = __float2bfloat16(xn);
    }
}

// ---------------- pooling + head ----------------
__global__ void k_pcnt(const void* __restrict__ bv, const void* __restrict__ bp) {
    int is64 = g_is64;
    int gid = blockIdx.x * blockDim.x + threadIdx.x;
    if (gid >= 2 * NN) return;
    int t = gid / NN, i = gid - t * NN;
    int g = t ? idx_at(bp, i, is64) : idx_at(bv, i, is64);
    atomicAdd(&g_pcnt[t][g], 1);
}

__global__ void k_pool(const float* __restrict__ x0, const void* __restrict__ bv,
                       const void* __restrict__ bp, float* __restrict__ pool0) {
    int is64 = g_is64;
    int t = blockIdx.y;
    const float* x = x0 + (long long)t * NN * HH;
    const void* batch = t ? bp : bv;
    float* pool = pool0 + t * GG * HH;
    int c = threadIdx.x;
    int r0 = blockIdx.x * 64;
    int r1 = min(r0 + 64, NN);
    float local = 0.f;
    int gprev = -1;
    for (int r = r0; r < r1; r++) {
        int g = idx_at(batch, r, is64);
        if (g != gprev) {
            if (gprev >= 0) atomicAdd(&pool[gprev * HH + c], local);
            local = 0.f;
            gprev = g;
        }
        local += x[(long long)r * HH + c];
    }
    if (gprev >= 0) atomicAdd(&pool[gprev * HH + c], local);
}

__global__ void k_final(const float* __restrict__ Wo, const float* __restrict__ bo,
                        float* __restrict__ out) {
    int g = threadIdx.x >> 5, lane = threadIdx.x & 31;
    if (g >= GG) return;
    float cv = (float)max(g_pcnt[0][g], 1);
    float cp = (float)max(g_pcnt[1][g], 1);
    float s = 0.f;
    for (int c = lane; c < HH; c += 32)
        s += g_pool[0][g * HH + c] / cv * Wo[c] + g_pool[1][g * HH + c] / cp * Wo[HH + c];
#pragma unroll
    for (int off = 16; off; off >>= 1) s += __shfl_down_sync(0xffffffffu, s, off);
    if (lane == 0) out[g] = 1.0f / (1.0f + expf(-(s + bo[0])));
}

// ---------------- launcher ----------------
extern "C" void kernel_launch(void* const* d_in, const int* in_sizes, int n_in,
                              void* d_out, int out_size) {
    const float* x_vuln  = (const float*)d_in[0];
    const float* x_patch = (const float*)d_in[1];
    const float* W_emb   = (const float*)d_in[2];
    const float* b_emb   = (const float*)d_in[3];
    const float* W_l     = (const float*)d_in[4];
    const float* b_l     = (const float*)d_in[5];
    const float* W_r     = (const float*)d_in[6];
    const float* gamma   = (const float*)d_in[7];
    const float* beta    = (const float*)d_in[8];
    const float* W_out   = (const float*)d_in[9];
    const float* b_out   = (const float*)d_in[10];
    const void* edge     = d_in[11];
    const void* batch_v  = d_in[12];
    const void* batch_p  = d_in[13];
    float* out = (float*)d_out;

    void* p;
    cudaGetSymbolAddress(&p, g_x);     float* x0 = (float*)p;
    cudaGetSymbolAddress(&p, g_accb);  float* a0 = (float*)p;  float* a1 = a0 + (size_t)NN * HH;
    cudaGetSymbolAddress(&p, g_tmpb);  __nv_bfloat16* tmpb = (__nv_bfloat16*)p;
    cudaGetSymbolAddress(&p, g_xb);    __nv_bfloat16* xb = (__nv_bfloat16*)p;
    cudaGetSymbolAddress(&p, g_inb);   __nv_bfloat16* inb = (__nv_bfloat16*)p;
    cudaGetSymbolAddress(&p, g_web);   __nv_bfloat16* web = (__nv_bfloat16*)p;
    cudaGetSymbolAddress(&p, g_wcat);  __nv_bfloat16* wcat = (__nv_bfloat16*)p;
    cudaGetSymbolAddress(&p, g_blsum); float* bls = (float*)p;
    cudaGetSymbolAddress(&p, g_deg);   void* degp = p;
    cudaGetSymbolAddress(&p, g_stats); float* stats = (float*)p;
    cudaGetSymbolAddress(&p, g_pool);  float* pool = (float*)p;
    cudaGetSymbolAddress(&p, g_pcnt);  void* pcnt = p;

    // index dtype detection + CSR build
    k_detect<<<1, 256>>>((const unsigned int*)edge);
    cudaMemsetAsync(degp, 0, sizeof(int) * NREL * NN, 0);
    k_hist<<<(NREL * EE + 255) / 256, 256>>>(edge);
    k_scan<<<NREL, 1024>>>();
    k_fill<<<(NREL * EE + 255) / 256, 256>>>(edge);

    // weight prep + input convert
    k_wprep<<<4096, 256>>>(W_emb, W_l, W_r, b_l);
    k_split<<<(2 * NN * DIN + 255) / 256, 256>>>(x_vuln, inb, NN * DIN);       // vuln half
    k_split<<<(NN * DIN + 255) / 256, 256>>>(x_patch, inb + NN * DIN, NN * DIN);

    const int MB = (NN + 127) / 128;
    size_t xs = (size_t)NN * HH;
    // embedding GEMMs (K=128), both types in one launch
    k_gemm<<<dim3(MB, 2, 2), 256>>>(inb, (long long)NN * DIN, web, (long long)HH * DIN,
                                    x0, (long long)xs, b_emb, HH,
                                    xb, (long long)xs, 0, 2, 1, NN, DIN);

    for (int layer = 0; layer < LL; layer++) {
        // merged self + 3-neighbor GEMM, both types in one launch
        k_gemm<<<dim3(MB, 8, 2), 256>>>(xb, (long long)xs,
                                        wcat + (size_t)(layer * 2) * 1024 * HH, (long long)1024 * HH,
                                        a0, (long long)xs, bls + layer * 2 * HH, HH,
                                        tmpb, (long long)3 * xs, (long long)xs,
                                        2, 0, NN, HH);
        // gather-mean
        int aggBlocks = (NN * 32 + 255) / 256;
        k_agg<<<aggBlocks, 256>>>(0, 1, 3, a0);
        k_agg<<<aggBlocks, 256>>>(2, 4, 5, a1);
        // batchnorm + relu (+ residual)
        cudaMemsetAsync(stats, 0, sizeof(float) * 2 * 2 * HH, 0);
        k_bnstats<<<dim3(128, 2), 256>>>(a0, stats);
        k_bnapply<<<dim3(256, 2), 256>>>(a0, x0, xb, stats,
                                         gamma + layer * 2 * HH, beta + layer * 2 * HH, layer > 0);
    }

    // pooling + head
    cudaMemsetAsync(pool, 0, sizeof(float) * 2 * GG * HH, 0);
    cudaMemsetAsync(pcnt, 0, sizeof(int) * 2 * GG, 0);
    k_pcnt<<<(2 * NN + 255) / 256, 256>>>(batch_v, batch_p);
    k_pool<<<dim3((NN + 63) / 64, 2), 256>>>(x0, batch_v, batch_p, pool);
    k_final<<<1, 1024>>>(W_out, b_out, out);
}